// round 2
// baseline (speedup 1.0000x reference)
#include <cuda_runtime.h>
#include <cuda_bf16.h>
#include <math.h>

// Problem constants (fixed shapes from reference)
#define T_TOK   8192          // B*S
#define DDIM    1024
#define HDIM    4096
#define NEXP    8
#define KSEL    1024          // top_k per expert = T/E

// ---------------- device scratch (no allocations allowed) ----------------
__device__ double g_probs[NEXP * T_TOK];         // [E][T] transposed probs (fp64 truth)
__device__ int    g_sel[NEXP * KSEL];            // selected token ids (sorted desc by prob)
__device__ float  g_wts[NEXP * KSEL];            // gating weights
__device__ float  g_h[(size_t)NEXP * KSEL * HDIM]; // hidden activations, 128 MiB

// ---------------- router: fp64 logits + fp64 softmax probs ----------------
__global__ void router_kernel(const float* __restrict__ x,
                              const float* __restrict__ rw,
                              float* __restrict__ logits_out) {
    const int t = blockIdx.x;
    const int tid = threadIdx.x;                 // 256 threads
    const float* xr = x + (size_t)t * DDIM;

    double acc[NEXP];
#pragma unroll
    for (int e = 0; e < NEXP; e++) acc[e] = 0.0;

    const int k = tid * 4;                       // 256*4 = 1024, one float4 each
    float4 xv = *(const float4*)(xr + k);
#pragma unroll
    for (int e = 0; e < NEXP; e++) {
        float4 wv = *(const float4*)(rw + e * DDIM + k);
        acc[e] = fma((double)xv.x, (double)wv.x, acc[e]);
        acc[e] = fma((double)xv.y, (double)wv.y, acc[e]);
        acc[e] = fma((double)xv.z, (double)wv.z, acc[e]);
        acc[e] = fma((double)xv.w, (double)wv.w, acc[e]);
    }
    // warp reduce (fp64 — order-insensitive at 1e-16)
#pragma unroll
    for (int e = 0; e < NEXP; e++)
#pragma unroll
        for (int o = 16; o; o >>= 1)
            acc[e] += __shfl_xor_sync(0xffffffffu, acc[e], o);

    __shared__ double red[NEXP][8];
    const int wid = tid >> 5, lid = tid & 31;
    if (lid == 0)
#pragma unroll
        for (int e = 0; e < NEXP; e++) red[e][wid] = acc[e];
    __syncthreads();

    if (tid == 0) {
        double l[NEXP], mx = -1e300;
#pragma unroll
        for (int e = 0; e < NEXP; e++) {
            double s = 0.0;
#pragma unroll
            for (int w = 0; w < 8; w++) s += red[e][w];
            l[e] = s;
            mx = fmax(mx, s);
        }
        double p[NEXP], sum = 0.0;
#pragma unroll
        for (int e = 0; e < NEXP; e++) { p[e] = exp(l[e] - mx); sum += p[e]; }
#pragma unroll
        for (int e = 0; e < NEXP; e++) {
            if (logits_out) logits_out[(size_t)t * NEXP + e] = (float)l[e];
            g_probs[(size_t)e * T_TOK + t] = p[e] / sum;
        }
    }
}

// ---------------- per-expert top-k via full bitonic sort ----------------
// Key packs the top 51 bits of the positive fp64 prob with a 13-bit inverted
// index: descending sort => prob desc, low-index-first tie-break at 2^-39
// relative granularity (far below the fp64 computation error).
__global__ void topk_kernel(float* __restrict__ sel_out) {
    extern __shared__ unsigned long long key[];  // 8192 * 8B = 64 KB
    const int e = blockIdx.x;
    const int tid = threadIdx.x;                 // 1024 threads

    for (int i = tid; i < T_TOK; i += 1024) {
        double p = g_probs[(size_t)e * T_TOK + i]; // softmax -> (0,1), positive
        unsigned long long db = __double_as_longlong(p); // monotonic for positive
        key[i] = (db & ~0x1FFFULL) | (unsigned long long)(8191 - i);
    }
    __syncthreads();

    // bitonic sort, descending by packed key
    for (int k = 2; k <= T_TOK; k <<= 1) {
        for (int j = k >> 1; j > 0; j >>= 1) {
            for (int i = tid; i < T_TOK; i += 1024) {
                int l = i ^ j;
                if (l > i) {
                    unsigned long long a = key[i], b = key[l];
                    bool descend = ((i & k) == 0);
                    if ((a < b) == descend) { key[i] = b; key[l] = a; }
                }
            }
            __syncthreads();
        }
    }

    // first KSEL entries are the top-k in descending order
    unsigned long long kk = key[tid];
    int idx = 8191 - (int)(kk & 0x1FFFULL);
    double val = __longlong_as_double((long long)(kk & ~0x1FFFULL));
    g_sel[e * KSEL + tid] = idx;
    g_wts[e * KSEL + tid] = (float)val;
    if (sel_out) sel_out[e * KSEL + tid] = (float)idx;
}

// ---------------- SGEMM tiles: 128x128x8, 256 threads, 8x8 microtile ----------------
#define BM 128
#define BN 128
#define BK 8

__device__ __forceinline__ float gelu_exact(float v) {
    return 0.5f * v * (1.0f + erff(v * 0.7071067811865476f));
}

// h[e] = gelu( x[sel[e]] @ w1[e] + b1[e] )   : M=1024, N=4096, K=1024
__global__ __launch_bounds__(256, 2)
void gemm1_kernel(const float* __restrict__ x,
                  const float* __restrict__ w1,
                  const float* __restrict__ b1) {
    const int e  = blockIdx.z;
    const int bm = blockIdx.y;   // 0..7
    const int bn = blockIdx.x;   // 0..31

    __shared__ float As[2][BK][BM];
    __shared__ float Bs[2][BK][BN];
    __shared__ int   rows[BM];

    const int tid = threadIdx.x;
    if (tid < BM) rows[tid] = g_sel[e * KSEL + bm * BM + tid];
    __syncthreads();

    const int la_m = tid >> 1;
    const int la_k = (tid & 1) * 4;
    const int lb_k = tid >> 5;
    const int lb_n = (tid & 31) * 4;

    const float* Aptr = x + (size_t)rows[la_m] * DDIM + la_k;
    const float* Bptr = w1 + (size_t)e * DDIM * HDIM + (size_t)lb_k * HDIM + bn * BN + lb_n;

    float4 a_ld = *(const float4*)Aptr;
    float4 b_ld = *(const float4*)Bptr;
    As[0][la_k + 0][la_m] = a_ld.x; As[0][la_k + 1][la_m] = a_ld.y;
    As[0][la_k + 2][la_m] = a_ld.z; As[0][la_k + 3][la_m] = a_ld.w;
    *(float4*)&Bs[0][lb_k][lb_n] = b_ld;
    __syncthreads();

    float acc[8][8];
#pragma unroll
    for (int i = 0; i < 8; i++)
#pragma unroll
        for (int j = 0; j < 8; j++) acc[i][j] = 0.f;

    const int tx = tid & 15, ty = tid >> 4;
    const int KT = DDIM / BK;

    for (int kt = 0; kt < KT; kt++) {
        const int cur = kt & 1;
        if (kt + 1 < KT) {
            a_ld = *(const float4*)(Aptr + (kt + 1) * BK);
            b_ld = *(const float4*)(Bptr + (size_t)(kt + 1) * BK * HDIM);
        }
#pragma unroll
        for (int kk = 0; kk < BK; kk++) {
            float af[8], bf[8];
            *(float4*)&af[0] = *(const float4*)&As[cur][kk][ty * 4];
            *(float4*)&af[4] = *(const float4*)&As[cur][kk][64 + ty * 4];
            *(float4*)&bf[0] = *(const float4*)&Bs[cur][kk][tx * 4];
            *(float4*)&bf[4] = *(const float4*)&Bs[cur][kk][64 + tx * 4];
#pragma unroll
            for (int i = 0; i < 8; i++)
#pragma unroll
                for (int j = 0; j < 8; j++)
                    acc[i][j] = fmaf(af[i], bf[j], acc[i][j]);
        }
        if (kt + 1 < KT) {
            const int nxt = cur ^ 1;
            As[nxt][la_k + 0][la_m] = a_ld.x; As[nxt][la_k + 1][la_m] = a_ld.y;
            As[nxt][la_k + 2][la_m] = a_ld.z; As[nxt][la_k + 3][la_m] = a_ld.w;
            *(float4*)&Bs[nxt][lb_k][lb_n] = b_ld;
        }
        __syncthreads();
    }

#pragma unroll
    for (int ih = 0; ih < 2; ih++) {
#pragma unroll
        for (int i = 0; i < 4; i++) {
            const int m = ih * 64 + ty * 4 + i;
            const size_t hrow = ((size_t)e * KSEL + bm * BM + m) * HDIM + bn * BN;
#pragma unroll
            for (int jh = 0; jh < 2; jh++) {
                const int n0 = jh * 64 + tx * 4;
                const float4 bv = *(const float4*)(b1 + e * HDIM + bn * BN + n0);
                float4 v;
                v.x = gelu_exact(acc[ih * 4 + i][jh * 4 + 0] + bv.x);
                v.y = gelu_exact(acc[ih * 4 + i][jh * 4 + 1] + bv.y);
                v.z = gelu_exact(acc[ih * 4 + i][jh * 4 + 2] + bv.z);
                v.w = gelu_exact(acc[ih * 4 + i][jh * 4 + 3] + bv.w);
                *(float4*)&g_h[hrow + n0] = v;
            }
        }
    }
}

// out[e] = (h[e] @ w2[e] + b2[e]) * w ; atomic scatter-add to results
// M=1024, N=1024, K=4096
__global__ __launch_bounds__(256, 2)
void gemm2_kernel(const float* __restrict__ w2,
                  const float* __restrict__ b2,
                  float* __restrict__ res) {
    const int e  = blockIdx.z;
    const int bm = blockIdx.y;   // 0..7
    const int bn = blockIdx.x;   // 0..7

    __shared__ float As[2][BK][BM];
    __shared__ float Bs[2][BK][BN];
    __shared__ int   rows[BM];
    __shared__ float wv[BM];

    const int tid = threadIdx.x;
    if (tid < BM) {
        rows[tid] = g_sel[e * KSEL + bm * BM + tid];
        wv[tid]   = g_wts[e * KSEL + bm * BM + tid];
    }
    __syncthreads();

    const int la_m = tid >> 1;
    const int la_k = (tid & 1) * 4;
    const int lb_k = tid >> 5;
    const int lb_n = (tid & 31) * 4;

    const float* Aptr = g_h + ((size_t)e * KSEL + bm * BM + la_m) * HDIM + la_k;
    const float* Bptr = w2 + (size_t)e * HDIM * DDIM + (size_t)lb_k * DDIM + bn * BN + lb_n;

    float4 a_ld = *(const float4*)Aptr;
    float4 b_ld = *(const float4*)Bptr;
    As[0][la_k + 0][la_m] = a_ld.x; As[0][la_k + 1][la_m] = a_ld.y;
    As[0][la_k + 2][la_m] = a_ld.z; As[0][la_k + 3][la_m] = a_ld.w;
    *(float4*)&Bs[0][lb_k][lb_n] = b_ld;
    __syncthreads();

    float acc[8][8];
#pragma unroll
    for (int i = 0; i < 8; i++)
#pragma unroll
        for (int j = 0; j < 8; j++) acc[i][j] = 0.f;

    const int tx = tid & 15, ty = tid >> 4;
    const int KT = HDIM / BK;

    for (int kt = 0; kt < KT; kt++) {
        const int cur = kt & 1;
        if (kt + 1 < KT) {
            a_ld = *(const float4*)(Aptr + (kt + 1) * BK);
            b_ld = *(const float4*)(Bptr + (size_t)(kt + 1) * BK * DDIM);
        }
#pragma unroll
        for (int kk = 0; kk < BK; kk++) {
            float af[8], bf[8];
            *(float4*)&af[0] = *(const float4*)&As[cur][kk][ty * 4];
            *(float4*)&af[4] = *(const float4*)&As[cur][kk][64 + ty * 4];
            *(float4*)&bf[0] = *(const float4*)&Bs[cur][kk][tx * 4];
            *(float4*)&bf[4] = *(const float4*)&Bs[cur][kk][64 + tx * 4];
#pragma unroll
            for (int i = 0; i < 8; i++)
#pragma unroll
                for (int j = 0; j < 8; j++)
                    acc[i][j] = fmaf(af[i], bf[j], acc[i][j]);
        }
        if (kt + 1 < KT) {
            const int nxt = cur ^ 1;
            As[nxt][la_k + 0][la_m] = a_ld.x; As[nxt][la_k + 1][la_m] = a_ld.y;
            As[nxt][la_k + 2][la_m] = a_ld.z; As[nxt][la_k + 3][la_m] = a_ld.w;
            *(float4*)&Bs[nxt][lb_k][lb_n] = b_ld;
        }
        __syncthreads();
    }

#pragma unroll
    for (int ih = 0; ih < 2; ih++) {
#pragma unroll
        for (int i = 0; i < 4; i++) {
            const int m = ih * 64 + ty * 4 + i;
            const int token = rows[m];
            const float g = wv[m];
            float* rrow = res + (size_t)token * DDIM + bn * BN;
#pragma unroll
            for (int jh = 0; jh < 2; jh++) {
                const int n0 = jh * 64 + tx * 4;
                const float4 bv = *(const float4*)(b2 + e * DDIM + bn * BN + n0);
                atomicAdd(&rrow[n0 + 0], (acc[ih * 4 + i][jh * 4 + 0] + bv.x) * g);
                atomicAdd(&rrow[n0 + 1], (acc[ih * 4 + i][jh * 4 + 1] + bv.y) * g);
                atomicAdd(&rrow[n0 + 2], (acc[ih * 4 + i][jh * 4 + 2] + bv.z) * g);
                atomicAdd(&rrow[n0 + 3], (acc[ih * 4 + i][jh * 4 + 3] + bv.w) * g);
            }
        }
    }
}

// ---------------- launch ----------------
extern "C" void kernel_launch(void* const* d_in, const int* in_sizes, int n_in,
                              void* d_out, int out_size) {
    const float* x   = (const float*)d_in[0];   // [4,2048,1024]
    const float* rw  = (const float*)d_in[1];   // [8,1024]
    const float* w1  = (const float*)d_in[2];   // [8,1024,4096]
    const float* b1  = (const float*)d_in[3];   // [8,4096]
    const float* w2  = (const float*)d_in[4];   // [8,4096,1024]
    const float* b2  = (const float*)d_in[5];   // [8,1024]

    float* out = (float*)d_out;
    float* res = out;                            // results [T, D]
    float* logits_out = nullptr;
    float* sel_out = nullptr;
    const long long TD = (long long)T_TOK * DDIM;
    if (out_size >= TD + T_TOK * NEXP) logits_out = out + TD;
    if (out_size >= TD + T_TOK * NEXP + NEXP * KSEL) sel_out = out + TD + T_TOK * NEXP;

    cudaMemsetAsync(res, 0, (size_t)TD * sizeof(float), 0);

    router_kernel<<<T_TOK, 256>>>(x, rw, logits_out);

    cudaFuncSetAttribute(topk_kernel, cudaFuncAttributeMaxDynamicSharedMemorySize,
                         T_TOK * (int)sizeof(unsigned long long));
    topk_kernel<<<NEXP, 1024, T_TOK * sizeof(unsigned long long)>>>(sel_out);

    gemm1_kernel<<<dim3(HDIM / BN, KSEL / BM, NEXP), 256>>>(x, w1, b1);
    gemm2_kernel<<<dim3(DDIM / BN, KSEL / BM, NEXP), 256>>>(w2, b2, res);
}

// round 4
// speedup vs baseline: 1.1630x; 1.1630x over previous
#include <cuda_runtime.h>
#include <cuda_bf16.h>
#include <math.h>
#include <stdint.h>
#include <mma.h>

using namespace nvcuda;

// Problem constants
#define T_TOK   8192
#define DDIM    1024
#define HDIM    4096
#define NEXP    8
#define KSEL    1024

// ---------------- device scratch ----------------
__device__ double g_probs[NEXP * T_TOK];
__device__ int    g_sel[NEXP * KSEL];
__device__ float  g_wts[NEXP * KSEL];
__device__ float  g_xg[(size_t)NEXP * KSEL * DDIM];    // gathered A rows (32 MB)
__device__ float  g_h [(size_t)NEXP * KSEL * HDIM];    // gemm1 output (128 MB)

__device__ __forceinline__ uint32_t smem_u32(const void* p) {
    uint32_t a;
    asm("{ .reg .u64 t; cvta.to.shared.u64 t, %1; cvt.u32.u64 %0, t; }" : "=r"(a) : "l"(p));
    return a;
}
__device__ __forceinline__ void cpasync16(uint32_t dst, const void* src) {
    asm volatile("cp.async.cg.shared.global [%0], [%1], 16;" :: "r"(dst), "l"(src) : "memory");
}
__device__ __forceinline__ float gelu_exact(float v) {
    return 0.5f * v * (1.0f + erff(v * 0.7071067811865476f));
}

// ================= router (fp64) =================
__global__ void router_kernel(const float* __restrict__ x,
                              const float* __restrict__ rw,
                              float* __restrict__ logits_out) {
    const int t = blockIdx.x;
    const int tid = threadIdx.x;
    const float* xr = x + (size_t)t * DDIM;
    double acc[NEXP];
#pragma unroll
    for (int e = 0; e < NEXP; e++) acc[e] = 0.0;
    const int k = tid * 4;
    float4 xv = *(const float4*)(xr + k);
#pragma unroll
    for (int e = 0; e < NEXP; e++) {
        float4 wv = *(const float4*)(rw + e * DDIM + k);
        acc[e] = fma((double)xv.x, (double)wv.x, acc[e]);
        acc[e] = fma((double)xv.y, (double)wv.y, acc[e]);
        acc[e] = fma((double)xv.z, (double)wv.z, acc[e]);
        acc[e] = fma((double)xv.w, (double)wv.w, acc[e]);
    }
#pragma unroll
    for (int e = 0; e < NEXP; e++)
#pragma unroll
        for (int o = 16; o; o >>= 1)
            acc[e] += __shfl_xor_sync(0xffffffffu, acc[e], o);
    __shared__ double red[NEXP][8];
    const int wid = tid >> 5, lid = tid & 31;
    if (lid == 0)
#pragma unroll
        for (int e = 0; e < NEXP; e++) red[e][wid] = acc[e];
    __syncthreads();
    if (tid == 0) {
        double l[NEXP], mx = -1e300;
#pragma unroll
        for (int e = 0; e < NEXP; e++) {
            double s = 0.0;
#pragma unroll
            for (int w = 0; w < 8; w++) s += red[e][w];
            l[e] = s; mx = fmax(mx, s);
        }
        double p[NEXP], sum = 0.0;
#pragma unroll
        for (int e = 0; e < NEXP; e++) { p[e] = exp(l[e] - mx); sum += p[e]; }
#pragma unroll
        for (int e = 0; e < NEXP; e++) {
            if (logits_out) logits_out[(size_t)t * NEXP + e] = (float)l[e];
            g_probs[(size_t)e * T_TOK + t] = p[e] / sum;
        }
    }
}

// ================= top-k (bitonic, fp64 keys) =================
__global__ void topk_kernel(float* __restrict__ sel_out) {
    extern __shared__ unsigned long long key[];
    const int e = blockIdx.x;
    const int tid = threadIdx.x;
    for (int i = tid; i < T_TOK; i += 1024) {
        double p = g_probs[(size_t)e * T_TOK + i];
        unsigned long long db = __double_as_longlong(p);
        key[i] = (db & ~0x1FFFULL) | (unsigned long long)(8191 - i);
    }
    __syncthreads();
    for (int k = 2; k <= T_TOK; k <<= 1) {
        for (int j = k >> 1; j > 0; j >>= 1) {
            for (int i = tid; i < T_TOK; i += 1024) {
                int l = i ^ j;
                if (l > i) {
                    unsigned long long a = key[i], b = key[l];
                    bool descend = ((i & k) == 0);
                    if ((a < b) == descend) { key[i] = b; key[l] = a; }
                }
            }
            __syncthreads();
        }
    }
    unsigned long long kk = key[tid];
    int idx = 8191 - (int)(kk & 0x1FFFULL);
    double val = __longlong_as_double((long long)(kk & ~0x1FFFULL));
    g_sel[e * KSEL + tid] = idx;
    g_wts[e * KSEL + tid] = (float)val;
    if (sel_out) sel_out[e * KSEL + tid] = (float)idx;
}

// ================= gather A rows =================
__global__ void gather_x_kernel(const float* __restrict__ x) {
    const int row = blockIdx.x;                 // 0..8191
    const int e = row >> 10, i = row & 1023;
    const int tok = g_sel[e * KSEL + i];
    const float4* s = (const float4*)(x + (size_t)tok * DDIM);
    float4* d = (float4*)(g_xg + (size_t)row * DDIM);
    d[threadIdx.x] = s[threadIdx.x];
}

// ================= wmma tf32 GEMM =================
// CTA tile 128x128, K-step 32, 8 warps (2 M x 4 N), warp tile 64x32.
#define BM   128
#define BN   128
#define BKK  32
#define LDA  36      // 32 + 4 pad (floats)
#define LDB  132     // 128 + 4 pad (floats)
#define LDC  132

#define OFF_TOK   0                  // 128 ints
#define OFF_WT    512                // 128 floats
#define OFF_BIAS  1024               // 128 floats
#define OFF_DATA  2048
#define A_STAGE   (BM * LDA * 4)     // 18432 B
#define B_STAGE   (BKK * LDB * 4)    // 16896 B
#define OFF_B     (OFF_DATA + 2 * A_STAGE)           // 38912
#define GEMM_SMEM (OFF_B + 2 * B_STAGE)              // 72704

template <bool G1>
__global__ __launch_bounds__(256)
void moe_wmma_kernel(const float* __restrict__ Bw,    // weights [E][K][N]
                     const float* __restrict__ bias,  // [E][N]
                     float* __restrict__ res) {
    extern __shared__ char smem[];
    const uint32_t sb = smem_u32(smem);
    const int tid = threadIdx.x;
    const int e = blockIdx.z, by = blockIdx.y, bx = blockIdx.x;

    constexpr int KDIM = G1 ? DDIM : HDIM;
    constexpr int NTOT = G1 ? HDIM : DDIM;
    constexpr int KI = KDIM / BKK;

    const float* A = G1 ? g_xg : g_h;
    const size_t aBase = (size_t)(e * 1024 + by * BM) * KDIM;
    const size_t bBase = (size_t)e * KDIM * NTOT + (size_t)bx * BN;

    // header
    if (tid < 128) {
        ((float*)(smem + OFF_BIAS))[tid] = bias[e * NTOT + bx * BN + tid];
        if (!G1) {
            ((int*)(smem + OFF_TOK))[tid] = g_sel[e * KSEL + by * BM + tid];
            ((float*)(smem + OFF_WT))[tid] = g_wts[e * KSEL + by * BM + tid];
        }
    }

    auto load_stage = [&](int kt, int buf) {
        const float* Ag = A + aBase + (size_t)kt * BKK;
        const uint32_t sA = sb + OFF_DATA + buf * A_STAGE;
#pragma unroll
        for (int i = 0; i < 4; i++) {
            const int c = tid + 256 * i;        // 0..1023
            const int r = c >> 3, c4 = c & 7;
            cpasync16(sA + (r * LDA + c4 * 4) * 4, Ag + (size_t)r * KDIM + c4 * 4);
        }
        const float* Bg = Bw + bBase + (size_t)kt * BKK * NTOT;
        const uint32_t sB = sb + OFF_B + buf * B_STAGE;
#pragma unroll
        for (int i = 0; i < 4; i++) {
            const int c = tid + 256 * i;
            const int r = c >> 5, c4 = c & 31;
            cpasync16(sB + (r * LDB + c4 * 4) * 4, Bg + (size_t)r * NTOT + c4 * 4);
        }
    };

    const int wid = tid >> 5;
    const int wm = wid & 1, wn = wid >> 1;

    wmma::fragment<wmma::accumulator, 16, 16, 8, float> acc[4][2];
#pragma unroll
    for (int i = 0; i < 4; i++)
#pragma unroll
        for (int j = 0; j < 2; j++) wmma::fill_fragment(acc[i][j], 0.0f);

    load_stage(0, 0);
    asm volatile("cp.async.commit_group;" ::: "memory");

    for (int kt = 0; kt < KI; kt++) {
        const int buf = kt & 1;
        if (kt + 1 < KI) {
            load_stage(kt + 1, buf ^ 1);
            asm volatile("cp.async.commit_group;" ::: "memory");
            asm volatile("cp.async.wait_group 1;" ::: "memory");
        } else {
            asm volatile("cp.async.wait_group 0;" ::: "memory");
        }
        __syncthreads();

        const float* as = (const float*)(smem + OFF_DATA + buf * A_STAGE) + wm * 64 * LDA;
        const float* bs = (const float*)(smem + OFF_B + buf * B_STAGE) + wn * 32;
#pragma unroll
        for (int ks = 0; ks < 4; ks++) {
            wmma::fragment<wmma::matrix_a, 16, 16, 8, wmma::precision::tf32, wmma::row_major> af[4];
            wmma::fragment<wmma::matrix_b, 16, 16, 8, wmma::precision::tf32, wmma::row_major> bf[2];
#pragma unroll
            for (int i = 0; i < 4; i++) {
                wmma::load_matrix_sync(af[i], as + (16 * i) * LDA + ks * 8, LDA);
#pragma unroll
                for (int t = 0; t < af[i].num_elements; t++)
                    af[i].x[t] = wmma::__float_to_tf32(af[i].x[t]);
            }
#pragma unroll
            for (int j = 0; j < 2; j++) {
                wmma::load_matrix_sync(bf[j], bs + (ks * 8) * LDB + 16 * j, LDB);
#pragma unroll
                for (int t = 0; t < bf[j].num_elements; t++)
                    bf[j].x[t] = wmma::__float_to_tf32(bf[j].x[t]);
            }
#pragma unroll
            for (int i = 0; i < 4; i++)
#pragma unroll
                for (int j = 0; j < 2; j++)
                    wmma::mma_sync(acc[i][j], af[i], bf[j], acc[i][j]);
        }
        __syncthreads();
    }

    // ---- stage C through smem (reuses the pipeline data region) ----
    float* Cs = (float*)(smem + OFF_DATA);
#pragma unroll
    for (int i = 0; i < 4; i++)
#pragma unroll
        for (int j = 0; j < 2; j++)
            wmma::store_matrix_sync(Cs + (wm * 64 + 16 * i) * LDC + wn * 32 + 16 * j,
                                    acc[i][j], LDC, wmma::mem_row_major);
    __syncthreads();

    const float* sbias = (const float*)(smem + OFF_BIAS);
    if (G1) {
#pragma unroll
        for (int q = 0; q < 16; q++) {
            const int v = tid * 16 + q;         // float4 index, 4096 total
            const int r = v >> 5, c4 = (v & 31) * 4;
            float4 c = *(const float4*)(Cs + r * LDC + c4);
            c.x = gelu_exact(c.x + sbias[c4 + 0]);
            c.y = gelu_exact(c.y + sbias[c4 + 1]);
            c.z = gelu_exact(c.z + sbias[c4 + 2]);
            c.w = gelu_exact(c.w + sbias[c4 + 3]);
            *(float4*)(g_h + ((size_t)e * 1024 + by * BM + r) * HDIM + bx * BN + c4) = c;
        }
    } else {
        const int* tok = (const int*)(smem + OFF_TOK);
        const float* wts = (const float*)(smem + OFF_WT);
#pragma unroll
        for (int q = 0; q < 16; q++) {
            const int v = tid * 16 + q;
            const int r = v >> 5, c4 = (v & 31) * 4;
            float4 c = *(const float4*)(Cs + r * LDC + c4);
            const float g = wts[r];
            float* dst = res + (size_t)tok[r] * DDIM + bx * BN + c4;
            atomicAdd(dst + 0, (c.x + sbias[c4 + 0]) * g);
            atomicAdd(dst + 1, (c.y + sbias[c4 + 1]) * g);
            atomicAdd(dst + 2, (c.z + sbias[c4 + 2]) * g);
            atomicAdd(dst + 3, (c.w + sbias[c4 + 3]) * g);
        }
    }
}

// ================= launch =================
extern "C" void kernel_launch(void* const* d_in, const int* in_sizes, int n_in,
                              void* d_out, int out_size) {
    const float* x  = (const float*)d_in[0];
    const float* rw = (const float*)d_in[1];
    const float* w1 = (const float*)d_in[2];
    const float* b1 = (const float*)d_in[3];
    const float* w2 = (const float*)d_in[4];
    const float* b2 = (const float*)d_in[5];

    float* out = (float*)d_out;
    float* res = out;
    float* logits_out = nullptr;
    float* sel_out = nullptr;
    const long long TD = (long long)T_TOK * DDIM;
    if (out_size >= TD + T_TOK * NEXP) logits_out = out + TD;
    if (out_size >= TD + T_TOK * NEXP + NEXP * KSEL) sel_out = out + TD + T_TOK * NEXP;

    cudaMemsetAsync(res, 0, (size_t)TD * sizeof(float), 0);

    router_kernel<<<T_TOK, 256>>>(x, rw, logits_out);

    cudaFuncSetAttribute(topk_kernel, cudaFuncAttributeMaxDynamicSharedMemorySize,
                         T_TOK * (int)sizeof(unsigned long long));
    topk_kernel<<<NEXP, 1024, T_TOK * sizeof(unsigned long long)>>>(sel_out);

    gather_x_kernel<<<NEXP * KSEL, 256>>>(x);

    cudaFuncSetAttribute(moe_wmma_kernel<true>,
                         cudaFuncAttributeMaxDynamicSharedMemorySize, GEMM_SMEM);
    cudaFuncSetAttribute(moe_wmma_kernel<false>,
                         cudaFuncAttributeMaxDynamicSharedMemorySize, GEMM_SMEM);

    moe_wmma_kernel<true><<<dim3(HDIM / BN, KSEL / BM, NEXP), 256, GEMM_SMEM>>>(w1, b1, nullptr);
    moe_wmma_kernel<false><<<dim3(DDIM / BN, KSEL / BM, NEXP), 256, GEMM_SMEM>>>(w2, b2, res);
}

// round 5
// speedup vs baseline: 1.1868x; 1.0205x over previous
#include <cuda_runtime.h>
#include <cuda_bf16.h>
#include <math.h>
#include <stdint.h>
#include <mma.h>

using namespace nvcuda;

// Problem constants
#define T_TOK   8192
#define DDIM    1024
#define HDIM    4096
#define NEXP    8
#define KSEL    1024

// ---------------- device scratch ----------------
__device__ double g_probs[NEXP * T_TOK];
__device__ int    g_sel[NEXP * KSEL];
__device__ float  g_wts[NEXP * KSEL];
__device__ float  g_xg [(size_t)NEXP * KSEL * DDIM];   // gathered A rows, tf32-rounded (32 MB)
__device__ float  g_h  [(size_t)NEXP * KSEL * HDIM];   // gemm1 out, tf32-rounded (128 MB)
__device__ float  g_w1r[(size_t)NEXP * DDIM * HDIM];   // w1 rna-rounded (128 MB)
__device__ float  g_w2r[(size_t)NEXP * HDIM * DDIM];   // w2 rna-rounded (128 MB)

__device__ __forceinline__ uint32_t smem_u32(const void* p) {
    uint32_t a;
    asm("{ .reg .u64 t; cvta.to.shared.u64 t, %1; cvt.u32.u64 %0, t; }" : "=r"(a) : "l"(p));
    return a;
}
__device__ __forceinline__ void cpasync16(uint32_t dst, const void* src) {
    asm volatile("cp.async.cg.shared.global [%0], [%1], 16;" :: "r"(dst), "l"(src) : "memory");
}
__device__ __forceinline__ float tf32_rna(float v) {
    uint32_t o;
    asm("cvt.rna.tf32.f32 %0, %1;" : "=r"(o) : "f"(v));
    return __uint_as_float(o);
}
__device__ __forceinline__ float gelu_exact(float v) {
    return 0.5f * v * (1.0f + erff(v * 0.7071067811865476f));
}

// ================= router (fp64) =================
__global__ void router_kernel(const float* __restrict__ x,
                              const float* __restrict__ rw,
                              float* __restrict__ logits_out) {
    const int t = blockIdx.x;
    const int tid = threadIdx.x;
    const float* xr = x + (size_t)t * DDIM;
    double acc[NEXP];
#pragma unroll
    for (int e = 0; e < NEXP; e++) acc[e] = 0.0;
    const int k = tid * 4;
    float4 xv = *(const float4*)(xr + k);
#pragma unroll
    for (int e = 0; e < NEXP; e++) {
        float4 wv = *(const float4*)(rw + e * DDIM + k);
        acc[e] = fma((double)xv.x, (double)wv.x, acc[e]);
        acc[e] = fma((double)xv.y, (double)wv.y, acc[e]);
        acc[e] = fma((double)xv.z, (double)wv.z, acc[e]);
        acc[e] = fma((double)xv.w, (double)wv.w, acc[e]);
    }
#pragma unroll
    for (int e = 0; e < NEXP; e++)
#pragma unroll
        for (int o = 16; o; o >>= 1)
            acc[e] += __shfl_xor_sync(0xffffffffu, acc[e], o);
    __shared__ double red[NEXP][8];
    const int wid = tid >> 5, lid = tid & 31;
    if (lid == 0)
#pragma unroll
        for (int e = 0; e < NEXP; e++) red[e][wid] = acc[e];
    __syncthreads();
    if (tid == 0) {
        double l[NEXP], mx = -1e300;
#pragma unroll
        for (int e = 0; e < NEXP; e++) {
            double s = 0.0;
#pragma unroll
            for (int w = 0; w < 8; w++) s += red[e][w];
            l[e] = s; mx = fmax(mx, s);
        }
        double p[NEXP], sum = 0.0;
#pragma unroll
        for (int e = 0; e < NEXP; e++) { p[e] = exp(l[e] - mx); sum += p[e]; }
#pragma unroll
        for (int e = 0; e < NEXP; e++) {
            if (logits_out) logits_out[(size_t)t * NEXP + e] = (float)l[e];
            g_probs[(size_t)e * T_TOK + t] = p[e] / sum;
        }
    }
}

// ================= top-k (bitonic, fp64 keys) =================
__global__ void topk_kernel(float* __restrict__ sel_out) {
    extern __shared__ unsigned long long key[];
    const int e = blockIdx.x;
    const int tid = threadIdx.x;
    for (int i = tid; i < T_TOK; i += 1024) {
        double p = g_probs[(size_t)e * T_TOK + i];
        unsigned long long db = __double_as_longlong(p);
        key[i] = (db & ~0x1FFFULL) | (unsigned long long)(8191 - i);
    }
    __syncthreads();
    for (int k = 2; k <= T_TOK; k <<= 1) {
        for (int j = k >> 1; j > 0; j >>= 1) {
            for (int i = tid; i < T_TOK; i += 1024) {
                int l = i ^ j;
                if (l > i) {
                    unsigned long long a = key[i], b = key[l];
                    bool descend = ((i & k) == 0);
                    if ((a < b) == descend) { key[i] = b; key[l] = a; }
                }
            }
            __syncthreads();
        }
    }
    unsigned long long kk = key[tid];
    int idx = 8191 - (int)(kk & 0x1FFFULL);
    double val = __longlong_as_double((long long)(kk & ~0x1FFFULL));
    g_sel[e * KSEL + tid] = idx;
    g_wts[e * KSEL + tid] = (float)val;
    if (sel_out) sel_out[e * KSEL + tid] = (float)idx;
}

// ================= gather A rows + rna round =================
__global__ void gather_x_kernel(const float* __restrict__ x) {
    const int row = blockIdx.x;                 // 0..8191
    const int e = row >> 10, i = row & 1023;
    const int tok = g_sel[e * KSEL + i];
    const float4* s = (const float4*)(x + (size_t)tok * DDIM);
    float4* d = (float4*)(g_xg + (size_t)row * DDIM);
    float4 v = s[threadIdx.x];
    v.x = tf32_rna(v.x); v.y = tf32_rna(v.y);
    v.z = tf32_rna(v.z); v.w = tf32_rna(v.w);
    d[threadIdx.x] = v;
}

// ================= elementwise rna-round weights =================
__global__ void round_tf32_kernel(const float* __restrict__ src, float* __restrict__ dst) {
    const size_t i = ((size_t)blockIdx.x * 256 + threadIdx.x) * 4;
    float4 v = *(const float4*)(src + i);
    v.x = tf32_rna(v.x); v.y = tf32_rna(v.y);
    v.z = tf32_rna(v.z); v.w = tf32_rna(v.w);
    *(float4*)(dst + i) = v;
}

// ================= wmma tf32 GEMM =================
// CTA tile 128x128, K-step 32, 8 warps (2 M x 4 N), warp tile 64x32.
// Operands pre-rounded to tf32-representable fp32 -> HW RZ truncation is identity,
// no in-fragment conversion needed.
#define BM   128
#define BN   128
#define BKK  32
#define LDA  36      // 32 + 4 pad (floats)
#define LDB  132     // 128 + 4 pad (floats)
#define LDC  132

#define OFF_TOK   0                  // 128 ints
#define OFF_WT    512                // 128 floats
#define OFF_BIAS  1024               // 128 floats
#define OFF_DATA  2048
#define A_STAGE   (BM * LDA * 4)     // 18432 B
#define B_STAGE   (BKK * LDB * 4)    // 16896 B
#define OFF_B     (OFF_DATA + 2 * A_STAGE)           // 38912
#define GEMM_SMEM (OFF_B + 2 * B_STAGE)              // 72704

template <bool G1>
__global__ __launch_bounds__(256, 2)
void moe_wmma_kernel(const float* __restrict__ Bw,    // weights [E][K][N], tf32-rounded
                     const float* __restrict__ bias,  // [E][N]
                     float* __restrict__ res) {
    extern __shared__ char smem[];
    const uint32_t sb = smem_u32(smem);
    const int tid = threadIdx.x;
    const int e = blockIdx.z, by = blockIdx.y, bx = blockIdx.x;

    constexpr int KDIM = G1 ? DDIM : HDIM;
    constexpr int NTOT = G1 ? HDIM : DDIM;
    constexpr int KI = KDIM / BKK;

    const float* A = G1 ? g_xg : g_h;
    const size_t aBase = (size_t)(e * 1024 + by * BM) * KDIM;
    const size_t bBase = (size_t)e * KDIM * NTOT + (size_t)bx * BN;

    if (tid < 128) {
        ((float*)(smem + OFF_BIAS))[tid] = bias[e * NTOT + bx * BN + tid];
        if (!G1) {
            ((int*)(smem + OFF_TOK))[tid] = g_sel[e * KSEL + by * BM + tid];
            ((float*)(smem + OFF_WT))[tid] = g_wts[e * KSEL + by * BM + tid];
        }
    }

    auto load_stage = [&](int kt, int buf) {
        const float* Ag = A + aBase + (size_t)kt * BKK;
        const uint32_t sA = sb + OFF_DATA + buf * A_STAGE;
#pragma unroll
        for (int i = 0; i < 4; i++) {
            const int c = tid + 256 * i;        // 0..1023
            const int r = c >> 3, c4 = c & 7;
            cpasync16(sA + (r * LDA + c4 * 4) * 4, Ag + (size_t)r * KDIM + c4 * 4);
        }
        const float* Bg = Bw + bBase + (size_t)kt * BKK * NTOT;
        const uint32_t sB = sb + OFF_B + buf * B_STAGE;
#pragma unroll
        for (int i = 0; i < 4; i++) {
            const int c = tid + 256 * i;
            const int r = c >> 5, c4 = c & 31;
            cpasync16(sB + (r * LDB + c4 * 4) * 4, Bg + (size_t)r * NTOT + c4 * 4);
        }
    };

    const int wid = tid >> 5;
    const int wm = wid & 1, wn = wid >> 1;

    wmma::fragment<wmma::accumulator, 16, 16, 8, float> acc[4][2];
#pragma unroll
    for (int i = 0; i < 4; i++)
#pragma unroll
        for (int j = 0; j < 2; j++) wmma::fill_fragment(acc[i][j], 0.0f);

    load_stage(0, 0);
    asm volatile("cp.async.commit_group;" ::: "memory");

    for (int kt = 0; kt < KI; kt++) {
        const int buf = kt & 1;
        if (kt + 1 < KI) {
            load_stage(kt + 1, buf ^ 1);
            asm volatile("cp.async.commit_group;" ::: "memory");
            asm volatile("cp.async.wait_group 1;" ::: "memory");
        } else {
            asm volatile("cp.async.wait_group 0;" ::: "memory");
        }
        __syncthreads();

        const float* as = (const float*)(smem + OFF_DATA + buf * A_STAGE) + wm * 64 * LDA;
        const float* bs = (const float*)(smem + OFF_B + buf * B_STAGE) + wn * 32;
#pragma unroll
        for (int ks = 0; ks < 4; ks++) {
            wmma::fragment<wmma::matrix_a, 16, 16, 8, wmma::precision::tf32, wmma::row_major> af[4];
            wmma::fragment<wmma::matrix_b, 16, 16, 8, wmma::precision::tf32, wmma::row_major> bf[2];
#pragma unroll
            for (int i = 0; i < 4; i++)
                wmma::load_matrix_sync(af[i], as + (16 * i) * LDA + ks * 8, LDA);
#pragma unroll
            for (int j = 0; j < 2; j++)
                wmma::load_matrix_sync(bf[j], bs + (ks * 8) * LDB + 16 * j, LDB);
#pragma unroll
            for (int i = 0; i < 4; i++)
#pragma unroll
                for (int j = 0; j < 2; j++)
                    wmma::mma_sync(acc[i][j], af[i], bf[j], acc[i][j]);
        }
        __syncthreads();
    }

    // ---- stage C through smem (reuses pipeline data region) ----
    float* Cs = (float*)(smem + OFF_DATA);
#pragma unroll
    for (int i = 0; i < 4; i++)
#pragma unroll
        for (int j = 0; j < 2; j++)
            wmma::store_matrix_sync(Cs + (wm * 64 + 16 * i) * LDC + wn * 32 + 16 * j,
                                    acc[i][j], LDC, wmma::mem_row_major);
    __syncthreads();

    const float* sbias = (const float*)(smem + OFF_BIAS);
    if (G1) {
#pragma unroll
        for (int q = 0; q < 16; q++) {
            const int v = tid * 16 + q;         // float4 index, 4096 total
            const int r = v >> 5, c4 = (v & 31) * 4;
            float4 c = *(const float4*)(Cs + r * LDC + c4);
            c.x = tf32_rna(gelu_exact(c.x + sbias[c4 + 0]));
            c.y = tf32_rna(gelu_exact(c.y + sbias[c4 + 1]));
            c.z = tf32_rna(gelu_exact(c.z + sbias[c4 + 2]));
            c.w = tf32_rna(gelu_exact(c.w + sbias[c4 + 3]));
            *(float4*)(g_h + ((size_t)e * 1024 + by * BM + r) * HDIM + bx * BN + c4) = c;
        }
    } else {
        const int* tok = (const int*)(smem + OFF_TOK);
        const float* wts = (const float*)(smem + OFF_WT);
#pragma unroll
        for (int q = 0; q < 16; q++) {
            const int v = tid * 16 + q;
            const int r = v >> 5, c4 = (v & 31) * 4;
            float4 c = *(const float4*)(Cs + r * LDC + c4);
            const float g = wts[r];
            float* dst = res + (size_t)tok[r] * DDIM + bx * BN + c4;
            atomicAdd(dst + 0, (c.x + sbias[c4 + 0]) * g);
            atomicAdd(dst + 1, (c.y + sbias[c4 + 1]) * g);
            atomicAdd(dst + 2, (c.z + sbias[c4 + 2]) * g);
            atomicAdd(dst + 3, (c.w + sbias[c4 + 3]) * g);
        }
    }
}

// ================= launch =================
extern "C" void kernel_launch(void* const* d_in, const int* in_sizes, int n_in,
                              void* d_out, int out_size) {
    const float* x  = (const float*)d_in[0];
    const float* rw = (const float*)d_in[1];
    const float* w1 = (const float*)d_in[2];
    const float* b1 = (const float*)d_in[3];
    const float* w2 = (const float*)d_in[4];
    const float* b2 = (const float*)d_in[5];

    float* out = (float*)d_out;
    float* res = out;
    float* logits_out = nullptr;
    float* sel_out = nullptr;
    const long long TD = (long long)T_TOK * DDIM;
    if (out_size >= TD + T_TOK * NEXP) logits_out = out + TD;
    if (out_size >= TD + T_TOK * NEXP + NEXP * KSEL) sel_out = out + TD + T_TOK * NEXP;

    cudaMemsetAsync(res, 0, (size_t)TD * sizeof(float), 0);

    router_kernel<<<T_TOK, 256>>>(x, rw, logits_out);

    cudaFuncSetAttribute(topk_kernel, cudaFuncAttributeMaxDynamicSharedMemorySize,
                         T_TOK * (int)sizeof(unsigned long long));
    topk_kernel<<<NEXP, 1024, T_TOK * sizeof(unsigned long long)>>>(sel_out);

    gather_x_kernel<<<NEXP * KSEL, 256>>>(x);

    const size_t WCNT = (size_t)NEXP * DDIM * HDIM;          // 33.5M floats
    float* w1r; cudaGetSymbolAddress((void**)&w1r, g_w1r);
    float* w2r; cudaGetSymbolAddress((void**)&w2r, g_w2r);
    round_tf32_kernel<<<(unsigned)(WCNT / (256 * 4)), 256>>>(w1, w1r);
    round_tf32_kernel<<<(unsigned)(WCNT / (256 * 4)), 256>>>(w2, w2r);

    cudaFuncSetAttribute(moe_wmma_kernel<true>,
                         cudaFuncAttributeMaxDynamicSharedMemorySize, GEMM_SMEM);
    cudaFuncSetAttribute(moe_wmma_kernel<false>,
                         cudaFuncAttributeMaxDynamicSharedMemorySize, GEMM_SMEM);

    moe_wmma_kernel<true><<<dim3(HDIM / BN, KSEL / BM, NEXP), 256, GEMM_SMEM>>>(w1r, b1, nullptr);
    moe_wmma_kernel<false><<<dim3(DDIM / BN, KSEL / BM, NEXP), 256, GEMM_SMEM>>>(w2r, b2, res);
}

// round 6
// speedup vs baseline: 1.2038x; 1.0143x over previous
#include <cuda_runtime.h>
#include <cuda_bf16.h>
#include <math.h>
#include <stdint.h>
#include <mma.h>

using namespace nvcuda;

// Problem constants
#define T_TOK   8192
#define DDIM    1024
#define HDIM    4096
#define NEXP    8
#define KSEL    1024

// ---------------- device scratch ----------------
__device__ double g_probs[NEXP * T_TOK];
__device__ int    g_sel[NEXP * KSEL];
__device__ float  g_wts[NEXP * KSEL];
__device__ float  g_xg [(size_t)NEXP * KSEL * DDIM];   // gathered A rows, tf32-rounded (32 MB)
__device__ float  g_h  [(size_t)NEXP * KSEL * HDIM];   // gemm1 out, tf32-rounded (128 MB)
__device__ float  g_w1r[(size_t)NEXP * DDIM * HDIM];   // w1 rna-rounded (128 MB)
__device__ float  g_w2r[(size_t)NEXP * HDIM * DDIM];   // w2 rna-rounded (128 MB)

__device__ __forceinline__ uint32_t smem_u32(const void* p) {
    uint32_t a;
    asm("{ .reg .u64 t; cvta.to.shared.u64 t, %1; cvt.u32.u64 %0, t; }" : "=r"(a) : "l"(p));
    return a;
}
__device__ __forceinline__ void cpasync16(uint32_t dst, const void* src) {
    asm volatile("cp.async.cg.shared.global [%0], [%1], 16;" :: "r"(dst), "l"(src) : "memory");
}
__device__ __forceinline__ float tf32_rna(float v) {
    uint32_t o;
    asm("cvt.rna.tf32.f32 %0, %1;" : "=r"(o) : "f"(v));
    return __uint_as_float(o);
}
__device__ __forceinline__ float gelu_exact(float v) {
    return 0.5f * v * (1.0f + erff(v * 0.7071067811865476f));
}

// ================= router (fp64) =================
__global__ void router_kernel(const float* __restrict__ x,
                              const float* __restrict__ rw,
                              float* __restrict__ logits_out) {
    const int t = blockIdx.x;
    const int tid = threadIdx.x;
    const float* xr = x + (size_t)t * DDIM;
    double acc[NEXP];
#pragma unroll
    for (int e = 0; e < NEXP; e++) acc[e] = 0.0;
    const int k = tid * 4;
    float4 xv = *(const float4*)(xr + k);
#pragma unroll
    for (int e = 0; e < NEXP; e++) {
        float4 wv = *(const float4*)(rw + e * DDIM + k);
        acc[e] = fma((double)xv.x, (double)wv.x, acc[e]);
        acc[e] = fma((double)xv.y, (double)wv.y, acc[e]);
        acc[e] = fma((double)xv.z, (double)wv.z, acc[e]);
        acc[e] = fma((double)xv.w, (double)wv.w, acc[e]);
    }
#pragma unroll
    for (int e = 0; e < NEXP; e++)
#pragma unroll
        for (int o = 16; o; o >>= 1)
            acc[e] += __shfl_xor_sync(0xffffffffu, acc[e], o);
    __shared__ double red[NEXP][8];
    const int wid = tid >> 5, lid = tid & 31;
    if (lid == 0)
#pragma unroll
        for (int e = 0; e < NEXP; e++) red[e][wid] = acc[e];
    __syncthreads();
    if (tid == 0) {
        double l[NEXP], mx = -1e300;
#pragma unroll
        for (int e = 0; e < NEXP; e++) {
            double s = 0.0;
#pragma unroll
            for (int w = 0; w < 8; w++) s += red[e][w];
            l[e] = s; mx = fmax(mx, s);
        }
        double p[NEXP], sum = 0.0;
#pragma unroll
        for (int e = 0; e < NEXP; e++) { p[e] = exp(l[e] - mx); sum += p[e]; }
#pragma unroll
        for (int e = 0; e < NEXP; e++) {
            if (logits_out) logits_out[(size_t)t * NEXP + e] = (float)l[e];
            g_probs[(size_t)e * T_TOK + t] = p[e] / sum;
        }
    }
}

// ================= top-k (bitonic, fp64 keys) =================
__global__ void topk_kernel(float* __restrict__ sel_out) {
    extern __shared__ unsigned long long key[];
    const int e = blockIdx.x;
    const int tid = threadIdx.x;
    for (int i = tid; i < T_TOK; i += 1024) {
        double p = g_probs[(size_t)e * T_TOK + i];
        unsigned long long db = __double_as_longlong(p);
        key[i] = (db & ~0x1FFFULL) | (unsigned long long)(8191 - i);
    }
    __syncthreads();
    for (int k = 2; k <= T_TOK; k <<= 1) {
        for (int j = k >> 1; j > 0; j >>= 1) {
            for (int i = tid; i < T_TOK; i += 1024) {
                int l = i ^ j;
                if (l > i) {
                    unsigned long long a = key[i], b = key[l];
                    bool descend = ((i & k) == 0);
                    if ((a < b) == descend) { key[i] = b; key[l] = a; }
                }
            }
            __syncthreads();
        }
    }
    unsigned long long kk = key[tid];
    int idx = 8191 - (int)(kk & 0x1FFFULL);
    double val = __longlong_as_double((long long)(kk & ~0x1FFFULL));
    g_sel[e * KSEL + tid] = idx;
    g_wts[e * KSEL + tid] = (float)val;
    if (sel_out) sel_out[e * KSEL + tid] = (float)idx;
}

// ================= gather A rows + rna round =================
__global__ void gather_x_kernel(const float* __restrict__ x) {
    const int row = blockIdx.x;                 // 0..8191
    const int e = row >> 10, i = row & 1023;
    const int tok = g_sel[e * KSEL + i];
    const float4* s = (const float4*)(x + (size_t)tok * DDIM);
    float4* d = (float4*)(g_xg + (size_t)row * DDIM);
    float4 v = s[threadIdx.x];
    v.x = tf32_rna(v.x); v.y = tf32_rna(v.y);
    v.z = tf32_rna(v.z); v.w = tf32_rna(v.w);
    d[threadIdx.x] = v;
}

// ================= elementwise rna-round weights =================
__global__ void round_tf32_kernel(const float* __restrict__ src, float* __restrict__ dst) {
    const size_t i = ((size_t)blockIdx.x * 256 + threadIdx.x) * 4;
    float4 v = *(const float4*)(src + i);
    v.x = tf32_rna(v.x); v.y = tf32_rna(v.y);
    v.z = tf32_rna(v.z); v.w = tf32_rna(v.w);
    *(float4*)(dst + i) = v;
}

// ================= wmma tf32 GEMM, 3-stage pipeline =================
// CTA tile 128x128, K-step 32, 8 warps (2 M x 4 N), warp tile 64x32.
// Operands pre-rounded to tf32; HW RZ truncation is identity.
#define BM   128
#define BN   128
#define BKK  32
#define LDA  36      // 32 + 4 pad
#define LDB  132     // 128 + 4 pad
#define LDC  132
#define STAGES 3

#define OFF_TOK   0                  // 128 ints
#define OFF_WT    512                // 128 floats
#define OFF_BIAS  1024               // 128 floats
#define OFF_DATA  2048
#define A_STAGE   (BM * LDA * 4)     // 18432 B
#define B_STAGE   (BKK * LDB * 4)    // 16896 B
#define STAGE_SZ  (A_STAGE + B_STAGE)                // 35328 B
#define GEMM_SMEM (OFF_DATA + STAGES * STAGE_SZ)     // 108032 B

template <bool G1>
__global__ __launch_bounds__(256, 2)
void moe_wmma_kernel(const float* __restrict__ Bw,    // weights [E][K][N], tf32-rounded
                     const float* __restrict__ bias,  // [E][N]
                     float* __restrict__ res) {
    extern __shared__ char smem[];
    const uint32_t sb = smem_u32(smem);
    const int tid = threadIdx.x;
    const int e = blockIdx.z, by = blockIdx.y, bx = blockIdx.x;

    constexpr int KDIM = G1 ? DDIM : HDIM;
    constexpr int NTOT = G1 ? HDIM : DDIM;
    constexpr int KI = KDIM / BKK;

    const float* A = G1 ? g_xg : g_h;
    const size_t aBase = (size_t)(e * 1024 + by * BM) * KDIM;
    const size_t bBase = (size_t)e * KDIM * NTOT + (size_t)bx * BN;

    if (tid < 128) {
        ((float*)(smem + OFF_BIAS))[tid] = bias[e * NTOT + bx * BN + tid];
        if (!G1) {
            ((int*)(smem + OFF_TOK))[tid] = g_sel[e * KSEL + by * BM + tid];
            ((float*)(smem + OFF_WT))[tid] = g_wts[e * KSEL + by * BM + tid];
        }
    }

    auto load_stage = [&](int kt, int buf) {
        const float* Ag = A + aBase + (size_t)kt * BKK;
        const uint32_t st = sb + OFF_DATA + buf * STAGE_SZ;
#pragma unroll
        for (int i = 0; i < 4; i++) {
            const int c = tid + 256 * i;        // 0..1023
            const int r = c >> 3, c4 = c & 7;
            cpasync16(st + (r * LDA + c4 * 4) * 4, Ag + (size_t)r * KDIM + c4 * 4);
        }
        const float* Bg = Bw + bBase + (size_t)kt * BKK * NTOT;
        const uint32_t sB = st + A_STAGE;
#pragma unroll
        for (int i = 0; i < 4; i++) {
            const int c = tid + 256 * i;
            const int r = c >> 5, c4 = c & 31;
            cpasync16(sB + (r * LDB + c4 * 4) * 4, Bg + (size_t)r * NTOT + c4 * 4);
        }
        asm volatile("cp.async.commit_group;" ::: "memory");
    };

    const int wid = tid >> 5;
    const int wm = wid & 1, wn = wid >> 1;

    wmma::fragment<wmma::accumulator, 16, 16, 8, float> acc[4][2];
#pragma unroll
    for (int i = 0; i < 4; i++)
#pragma unroll
        for (int j = 0; j < 2; j++) wmma::fill_fragment(acc[i][j], 0.0f);

    load_stage(0, 0);
    load_stage(1, 1);

    int buf = 0;
#pragma unroll 1
    for (int kt = 0; kt < KI; kt++) {
        if (kt < KI - 1) asm volatile("cp.async.wait_group 1;" ::: "memory");
        else             asm volatile("cp.async.wait_group 0;" ::: "memory");
        __syncthreads();

        // issue next-next stage before doing MMA work (keeps 2 loads in flight)
        if (kt + 2 < KI) {
            int nb = buf + 2; if (nb >= STAGES) nb -= STAGES;
            load_stage(kt + 2, nb);
        }

        const float* as = (const float*)(smem + OFF_DATA + buf * STAGE_SZ) + wm * 64 * LDA;
        const float* bs = (const float*)(smem + OFF_DATA + buf * STAGE_SZ + A_STAGE) + wn * 32;
#pragma unroll
        for (int ks = 0; ks < 4; ks++) {
            wmma::fragment<wmma::matrix_a, 16, 16, 8, wmma::precision::tf32, wmma::row_major> af[4];
            wmma::fragment<wmma::matrix_b, 16, 16, 8, wmma::precision::tf32, wmma::row_major> bf[2];
#pragma unroll
            for (int i = 0; i < 4; i++)
                wmma::load_matrix_sync(af[i], as + (16 * i) * LDA + ks * 8, LDA);
#pragma unroll
            for (int j = 0; j < 2; j++)
                wmma::load_matrix_sync(bf[j], bs + (ks * 8) * LDB + 16 * j, LDB);
#pragma unroll
            for (int i = 0; i < 4; i++)
#pragma unroll
                for (int j = 0; j < 2; j++)
                    wmma::mma_sync(acc[i][j], af[i], bf[j], acc[i][j]);
        }
        if (++buf == STAGES) buf = 0;
    }
    __syncthreads();

    // ---- stage C through smem (reuses pipeline data region) ----
    float* Cs = (float*)(smem + OFF_DATA);
#pragma unroll
    for (int i = 0; i < 4; i++)
#pragma unroll
        for (int j = 0; j < 2; j++)
            wmma::store_matrix_sync(Cs + (wm * 64 + 16 * i) * LDC + wn * 32 + 16 * j,
                                    acc[i][j], LDC, wmma::mem_row_major);
    __syncthreads();

    const float* sbias = (const float*)(smem + OFF_BIAS);
    if (G1) {
#pragma unroll
        for (int q = 0; q < 16; q++) {
            const int v = tid * 16 + q;         // float4 index, 4096 total
            const int r = v >> 5, c4 = (v & 31) * 4;
            float4 c = *(const float4*)(Cs + r * LDC + c4);
            c.x = tf32_rna(gelu_exact(c.x + sbias[c4 + 0]));
            c.y = tf32_rna(gelu_exact(c.y + sbias[c4 + 1]));
            c.z = tf32_rna(gelu_exact(c.z + sbias[c4 + 2]));
            c.w = tf32_rna(gelu_exact(c.w + sbias[c4 + 3]));
            *(float4*)(g_h + ((size_t)e * 1024 + by * BM + r) * HDIM + bx * BN + c4) = c;
        }
    } else {
        const int* tok = (const int*)(smem + OFF_TOK);
        const float* wts = (const float*)(smem + OFF_WT);
#pragma unroll
        for (int q = 0; q < 16; q++) {
            const int v = tid * 16 + q;
            const int r = v >> 5, c4 = (v & 31) * 4;
            float4 c = *(const float4*)(Cs + r * LDC + c4);
            const float g = wts[r];
            float* dst = res + (size_t)tok[r] * DDIM + bx * BN + c4;
            atomicAdd(dst + 0, (c.x + sbias[c4 + 0]) * g);
            atomicAdd(dst + 1, (c.y + sbias[c4 + 1]) * g);
            atomicAdd(dst + 2, (c.z + sbias[c4 + 2]) * g);
            atomicAdd(dst + 3, (c.w + sbias[c4 + 3]) * g);
        }
    }
}

// ================= launch =================
extern "C" void kernel_launch(void* const* d_in, const int* in_sizes, int n_in,
                              void* d_out, int out_size) {
    const float* x  = (const float*)d_in[0];
    const float* rw = (const float*)d_in[1];
    const float* w1 = (const float*)d_in[2];
    const float* b1 = (const float*)d_in[3];
    const float* w2 = (const float*)d_in[4];
    const float* b2 = (const float*)d_in[5];

    float* out = (float*)d_out;
    float* res = out;
    float* logits_out = nullptr;
    float* sel_out = nullptr;
    const long long TD = (long long)T_TOK * DDIM;
    if (out_size >= TD + T_TOK * NEXP) logits_out = out + TD;
    if (out_size >= TD + T_TOK * NEXP + NEXP * KSEL) sel_out = out + TD + T_TOK * NEXP;

    // fork-join side streams for the weight-rounding passes
    static cudaStream_t s1 = nullptr, s2 = nullptr;
    static cudaEvent_t ev0 = nullptr, ev1 = nullptr, ev2 = nullptr;
    if (!s1) {
        cudaStreamCreateWithFlags(&s1, cudaStreamNonBlocking);
        cudaStreamCreateWithFlags(&s2, cudaStreamNonBlocking);
        cudaEventCreateWithFlags(&ev0, cudaEventDisableTiming);
        cudaEventCreateWithFlags(&ev1, cudaEventDisableTiming);
        cudaEventCreateWithFlags(&ev2, cudaEventDisableTiming);
    }

    const size_t WCNT = (size_t)NEXP * DDIM * HDIM;
    float* w1r; cudaGetSymbolAddress((void**)&w1r, g_w1r);
    float* w2r; cudaGetSymbolAddress((void**)&w2r, g_w2r);

    cudaMemsetAsync(res, 0, (size_t)TD * sizeof(float), 0);

    cudaEventRecord(ev0, 0);
    cudaStreamWaitEvent(s1, ev0, 0);
    cudaStreamWaitEvent(s2, ev0, 0);
    round_tf32_kernel<<<(unsigned)(WCNT / (256 * 4)), 256, 0, s1>>>(w1, w1r);
    round_tf32_kernel<<<(unsigned)(WCNT / (256 * 4)), 256, 0, s2>>>(w2, w2r);
    cudaEventRecord(ev1, s1);
    cudaEventRecord(ev2, s2);

    router_kernel<<<T_TOK, 256>>>(x, rw, logits_out);

    cudaFuncSetAttribute(topk_kernel, cudaFuncAttributeMaxDynamicSharedMemorySize,
                         T_TOK * (int)sizeof(unsigned long long));
    topk_kernel<<<NEXP, 1024, T_TOK * sizeof(unsigned long long)>>>(sel_out);

    gather_x_kernel<<<NEXP * KSEL, 256>>>(x);

    cudaFuncSetAttribute(moe_wmma_kernel<true>,
                         cudaFuncAttributeMaxDynamicSharedMemorySize, GEMM_SMEM);
    cudaFuncSetAttribute(moe_wmma_kernel<false>,
                         cudaFuncAttributeMaxDynamicSharedMemorySize, GEMM_SMEM);

    cudaStreamWaitEvent(0, ev1, 0);
    moe_wmma_kernel<true><<<dim3(HDIM / BN, KSEL / BM, NEXP), 256, GEMM_SMEM>>>(w1r, b1, nullptr);
    cudaStreamWaitEvent(0, ev2, 0);
    moe_wmma_kernel<false><<<dim3(DDIM / BN, KSEL / BM, NEXP), 256, GEMM_SMEM>>>(w2r, b2, res);
}

// round 7
// speedup vs baseline: 2.1592x; 1.7936x over previous
#include <cuda_runtime.h>
#include <cuda_bf16.h>
#include <math.h>
#include <stdint.h>

// Problem constants
#define T_TOK   8192
#define DDIM    1024
#define HDIM    4096
#define NEXP    8
#define KSEL    1024

// ---------------- device scratch ----------------
// Packed operand layout (for both A and B of the MMA):
//   element (row r, col k):  kb=k>>3, rb=r>>3, h=(k>>2)&1, rr=r&7, kk=k&3
//   float offset = (((kb*RB + rb)*2 + h)*8 + rr)*4 + kk      (RB = rows/8)
// Each 16B chunk = 4 consecutive k of one row; each 128B block = one 8x4 LDSM matrix.
__device__ double g_probs[NEXP * T_TOK];
__device__ int    g_sel[NEXP * KSEL];
__device__ float  g_wts[NEXP * KSEL];
__device__ float  g_xg [(size_t)NEXP * KSEL * DDIM];   // gathered A, packed (32 MB)
__device__ float  g_h  [(size_t)NEXP * KSEL * HDIM];   // gemm1 out, packed (128 MB)
__device__ float  g_w1r[(size_t)NEXP * DDIM * HDIM];   // w1 packed+rounded (128 MB)
__device__ float  g_w2r[(size_t)NEXP * HDIM * DDIM];   // w2 packed+rounded (128 MB)

__device__ __forceinline__ uint32_t smem_u32(const void* p) {
    uint32_t a;
    asm("{ .reg .u64 t; cvta.to.shared.u64 t, %1; cvt.u32.u64 %0, t; }" : "=r"(a) : "l"(p));
    return a;
}
__device__ __forceinline__ void cpasync16(uint32_t dst, const void* src) {
    asm volatile("cp.async.cg.shared.global [%0], [%1], 16;" :: "r"(dst), "l"(src) : "memory");
}
__device__ __forceinline__ float tf32_rna(float v) {
    uint32_t o;
    asm("cvt.rna.tf32.f32 %0, %1;" : "=r"(o) : "f"(v));
    return __uint_as_float(o);
}
__device__ __forceinline__ float gelu_exact(float v) {
    return 0.5f * v * (1.0f + erff(v * 0.7071067811865476f));
}
__device__ __forceinline__ void ldsm_x4(uint32_t* r, uint32_t addr) {
    asm volatile("ldmatrix.sync.aligned.m8n8.x4.shared.b16 {%0,%1,%2,%3}, [%4];"
                 : "=r"(r[0]), "=r"(r[1]), "=r"(r[2]), "=r"(r[3]) : "r"(addr));
}
__device__ __forceinline__ void mma_16n8k8(float* d, const uint32_t* a, const uint32_t* b) {
    asm volatile(
        "mma.sync.aligned.m16n8k8.row.col.f32.tf32.tf32.f32 "
        "{%0,%1,%2,%3},{%4,%5,%6,%7},{%8,%9},{%0,%1,%2,%3};"
        : "+f"(d[0]), "+f"(d[1]), "+f"(d[2]), "+f"(d[3])
        : "r"(a[0]), "r"(a[1]), "r"(a[2]), "r"(a[3]), "r"(b[0]), "r"(b[1]));
}

// ================= router (fp64) =================
__global__ void router_kernel(const float* __restrict__ x,
                              const float* __restrict__ rw,
                              float* __restrict__ logits_out) {
    const int t = blockIdx.x;
    const int tid = threadIdx.x;
    const float* xr = x + (size_t)t * DDIM;
    double acc[NEXP];
#pragma unroll
    for (int e = 0; e < NEXP; e++) acc[e] = 0.0;
    const int k = tid * 4;
    float4 xv = *(const float4*)(xr + k);
#pragma unroll
    for (int e = 0; e < NEXP; e++) {
        float4 wv = *(const float4*)(rw + e * DDIM + k);
        acc[e] = fma((double)xv.x, (double)wv.x, acc[e]);
        acc[e] = fma((double)xv.y, (double)wv.y, acc[e]);
        acc[e] = fma((double)xv.z, (double)wv.z, acc[e]);
        acc[e] = fma((double)xv.w, (double)wv.w, acc[e]);
    }
#pragma unroll
    for (int e = 0; e < NEXP; e++)
#pragma unroll
        for (int o = 16; o; o >>= 1)
            acc[e] += __shfl_xor_sync(0xffffffffu, acc[e], o);
    __shared__ double red[NEXP][8];
    const int wid = tid >> 5, lid = tid & 31;
    if (lid == 0)
#pragma unroll
        for (int e = 0; e < NEXP; e++) red[e][wid] = acc[e];
    __syncthreads();
    if (tid == 0) {
        double l[NEXP], mx = -1e300;
#pragma unroll
        for (int e = 0; e < NEXP; e++) {
            double s = 0.0;
#pragma unroll
            for (int w = 0; w < 8; w++) s += red[e][w];
            l[e] = s; mx = fmax(mx, s);
        }
        double p[NEXP], sum = 0.0;
#pragma unroll
        for (int e = 0; e < NEXP; e++) { p[e] = exp(l[e] - mx); sum += p[e]; }
#pragma unroll
        for (int e = 0; e < NEXP; e++) {
            if (logits_out) logits_out[(size_t)t * NEXP + e] = (float)l[e];
            g_probs[(size_t)e * T_TOK + t] = p[e] / sum;
        }
    }
}

// ================= top-k (bitonic, fp64 keys) =================
__global__ void topk_kernel(float* __restrict__ sel_out) {
    extern __shared__ unsigned long long key[];
    const int e = blockIdx.x;
    const int tid = threadIdx.x;
    for (int i = tid; i < T_TOK; i += 1024) {
        double p = g_probs[(size_t)e * T_TOK + i];
        unsigned long long db = __double_as_longlong(p);
        key[i] = (db & ~0x1FFFULL) | (unsigned long long)(8191 - i);
    }
    __syncthreads();
    for (int k = 2; k <= T_TOK; k <<= 1) {
        for (int j = k >> 1; j > 0; j >>= 1) {
            for (int i = tid; i < T_TOK; i += 1024) {
                int l = i ^ j;
                if (l > i) {
                    unsigned long long a = key[i], b = key[l];
                    bool descend = ((i & k) == 0);
                    if ((a < b) == descend) { key[i] = b; key[l] = a; }
                }
            }
            __syncthreads();
        }
    }
    unsigned long long kk = key[tid];
    int idx = 8191 - (int)(kk & 0x1FFFULL);
    double val = __longlong_as_double((long long)(kk & ~0x1FFFULL));
    g_sel[e * KSEL + tid] = idx;
    g_wts[e * KSEL + tid] = (float)val;
    if (sel_out) sel_out[e * KSEL + tid] = (float)idx;
}

// ================= gather A rows -> packed layout + rna =================
__global__ void gather_x_kernel(const float* __restrict__ x) {
    const int row = blockIdx.x;                 // 0..8191
    const int e = row >> 10, i = row & 1023;
    const int tok = g_sel[e * KSEL + i];
    const int tid = threadIdx.x;                // 0..255, one float4
    float4 v = ((const float4*)(x + (size_t)tok * DDIM))[tid];
    v.x = tf32_rna(v.x); v.y = tf32_rna(v.y);
    v.z = tf32_rna(v.z); v.w = tf32_rna(v.w);
    const int kb = tid >> 1, h = tid & 1;       // c4 = tid*4
    const int rb = i >> 3, rr = i & 7;
    const size_t off = ((((size_t)e * 128 + kb) * 128 + rb) * 2 + h) * 32 + rr * 4;
    *(float4*)(g_xg + off) = v;
}

// ================= weight pack: [E][K][N] -> packed(r=n, k) + rna =================
// grid (N/32, K/32, E), block (32, 8)
__global__ void pack_w_kernel(const float* __restrict__ src, float* __restrict__ dst,
                              int K, int N) {
    __shared__ float t[32][33];
    const int e = blockIdx.z;
    const int k0 = blockIdx.y * 32, n0 = blockIdx.x * 32;
    const int tx = threadIdx.x, ty = threadIdx.y;
    const float* s = src + (size_t)e * K * N;
#pragma unroll
    for (int j = 0; j < 4; j++)
        t[ty + 8 * j][tx] = s[(size_t)(k0 + ty + 8 * j) * N + n0 + tx];
    __syncthreads();
    // thread: n-local = tx, k-chunk = ty (4 floats)
    float4 v;
    v.x = tf32_rna(t[ty * 4 + 0][tx]);
    v.y = tf32_rna(t[ty * 4 + 1][tx]);
    v.z = tf32_rna(t[ty * 4 + 2][tx]);
    v.w = tf32_rna(t[ty * 4 + 3][tx]);
    const int n = n0 + tx, kv = k0 + ty * 4;
    const int kb = kv >> 3, h = (kv >> 2) & 1;
    const int nb = n >> 3, nn = n & 7;
    const size_t KB = (size_t)(K >> 3), NB = (size_t)(N >> 3);
    const size_t off = ((((size_t)e * KB + kb) * NB + nb) * 2 + h) * 32 + nn * 4;
    *(float4*)(dst + off) = v;
}

// ================= mma.m16n8k8 tf32 GEMM, packed operands, 3 stages =================
// CTA 128x128, K-step 32, 8 warps (2m x 4n), warp tile 64x32.
#define BM   128
#define BN   128
#define LDC  132
#define STAGES 3

#define OFF_TOK   0                  // 128 ints
#define OFF_WT    512                // 128 floats
#define OFF_BIAS  1024               // 128 floats
#define OFF_DATA  2048
#define A_BYTES_S 16384              // per stage
#define STAGE_SZ  32768
#define GEMM_SMEM (OFF_DATA + STAGES * STAGE_SZ)   // 100352

template <bool G1>
__global__ __launch_bounds__(256, 2)
void moe_mma_kernel(const float* __restrict__ Bw,     // packed weights
                    const float* __restrict__ bias,   // [E][N]
                    float* __restrict__ res) {
    extern __shared__ char smem[];
    const uint32_t sb = smem_u32(smem);
    const int tid = threadIdx.x;
    const int lane = tid & 31;
    const int e = blockIdx.z, by = blockIdx.y, bx = blockIdx.x;

    constexpr int KDIM = G1 ? DDIM : HDIM;
    constexpr int NTOT = G1 ? HDIM : DDIM;
    constexpr int KI = KDIM / 32;
    constexpr int RB = 128;              // 1024 rows / 8 per expert
    constexpr int NB = NTOT / 8;

    const float* A = (G1 ? g_xg : g_h) + (size_t)e * KDIM * 1024;
    const float* B = Bw + (size_t)e * KDIM * NTOT;

    if (tid < 128) {
        ((float*)(smem + OFF_BIAS))[tid] = bias[e * NTOT + bx * BN + tid];
        if (!G1) {
            ((int*)(smem + OFF_TOK))[tid] = g_sel[e * KSEL + by * BM + tid];
            ((float*)(smem + OFF_WT))[tid] = g_wts[e * KSEL + by * BM + tid];
        }
    }

    // stage load: 2048 chunks of 16B; A chunks [kb][rb16][h][rr], B likewise.
    auto load_stage = [&](int kt, int buf) {
        const uint32_t st = sb + OFF_DATA + buf * STAGE_SZ;
#pragma unroll
        for (int i = 0; i < 8; i++) {
            const int c = tid + 256 * i;         // 0..2047
            const int kb = (c >> 8) & 3, inner = c & 255;
            const float* src;
            if (c < 1024)
                src = A + ((size_t)(kt * 4 + kb) * RB + by * 16) * 64 + inner * 4;
            else
                src = B + ((size_t)(kt * 4 + kb) * NB + bx * 16) * 64 + inner * 4;
            cpasync16(st + c * 16, src);
        }
        asm volatile("cp.async.commit_group;" ::: "memory");
    };

    const int wid = tid >> 5;
    const int wm = wid & 1, wn = wid >> 1;
    const int msel = lane >> 3;
    // per-thread LDSM row-address offsets (16B units)
    const uint32_t aoff = (uint32_t)(((msel & 1) * 16 + (msel >> 1) * 8 + (lane & 7)));
    const uint32_t boff = (uint32_t)(((msel >> 1) * 16 + (msel & 1) * 8 + (lane & 7)));
    const uint32_t aWarp = (uint32_t)(wm * 8 * 16 + aoff) * 16;          // bytes
    const uint32_t bWarp = (uint32_t)A_BYTES_S + ((uint32_t)(wn * 4 * 16 + boff) * 16);

    float acc[4][4][4];
#pragma unroll
    for (int i = 0; i < 4; i++)
#pragma unroll
        for (int j = 0; j < 4; j++)
#pragma unroll
            for (int q = 0; q < 4; q++) acc[i][j][q] = 0.f;

    load_stage(0, 0);
    load_stage(1, 1);

    int buf = 0;
#pragma unroll 1
    for (int kt = 0; kt < KI; kt++) {
        if (kt < KI - 1) asm volatile("cp.async.wait_group 1;" ::: "memory");
        else             asm volatile("cp.async.wait_group 0;" ::: "memory");
        __syncthreads();
        if (kt + 2 < KI) {
            int nb2 = buf + 2; if (nb2 >= STAGES) nb2 -= STAGES;
            load_stage(kt + 2, nb2);
        }
        const uint32_t st = sb + OFF_DATA + buf * STAGE_SZ;
#pragma unroll
        for (int ks = 0; ks < 4; ks++) {
            const uint32_t ksb = st + ks * 4096;
            uint32_t a[4][4], b[4][2];
#pragma unroll
            for (int mt = 0; mt < 4; mt++)
                ldsm_x4(a[mt], ksb + aWarp + mt * 512);
#pragma unroll
            for (int p = 0; p < 2; p++) {
                uint32_t r[4];
                ldsm_x4(r, ksb + bWarp + p * 512);
                b[2 * p][0] = r[0]; b[2 * p][1] = r[1];
                b[2 * p + 1][0] = r[2]; b[2 * p + 1][1] = r[3];
            }
#pragma unroll
            for (int mt = 0; mt < 4; mt++)
#pragma unroll
                for (int nt = 0; nt < 4; nt++)
                    mma_16n8k8(acc[mt][nt], a[mt], b[nt]);
        }
        if (++buf == STAGES) buf = 0;
    }
    __syncthreads();

    // ---- stage C through smem ----
    float* Cs = (float*)(smem + OFF_DATA);
#pragma unroll
    for (int mt = 0; mt < 4; mt++)
#pragma unroll
        for (int nt = 0; nt < 4; nt++) {
            const int r0 = wm * 64 + mt * 16 + (lane >> 2);
            const int cc = wn * 32 + nt * 8 + (lane & 3) * 2;
            *(float2*)&Cs[r0 * LDC + cc]       = make_float2(acc[mt][nt][0], acc[mt][nt][1]);
            *(float2*)&Cs[(r0 + 8) * LDC + cc] = make_float2(acc[mt][nt][2], acc[mt][nt][3]);
        }
    __syncthreads();

    const float* sbias = (const float*)(smem + OFF_BIAS);
    if (G1) {
#pragma unroll
        for (int q = 0; q < 16; q++) {
            const int v = tid * 16 + q;          // float4 idx, 4096 total
            const int r = v >> 5, c4 = (v & 31) * 4;
            float4 c = *(const float4*)(Cs + r * LDC + c4);
            c.x = tf32_rna(gelu_exact(c.x + sbias[c4 + 0]));
            c.y = tf32_rna(gelu_exact(c.y + sbias[c4 + 1]));
            c.z = tf32_rna(gelu_exact(c.z + sbias[c4 + 2]));
            c.w = tf32_rna(gelu_exact(c.w + sbias[c4 + 3]));
            // packed write into g_h (A of GEMM2): row m, k = global n
            const int n = bx * BN + c4;
            const int kb = n >> 3, h = (n >> 2) & 1;
            const int m = by * BM + r;
            const int rb = m >> 3, rr = m & 7;
            const size_t off = ((((size_t)e * 512 + kb) * 128 + rb) * 2 + h) * 32 + rr * 4;
            *(float4*)(g_h + off) = c;
        }
    } else {
        const int* tok = (const int*)(smem + OFF_TOK);
        const float* wts = (const float*)(smem + OFF_WT);
#pragma unroll
        for (int q = 0; q < 16; q++) {
            const int v = tid * 16 + q;
            const int r = v >> 5, c4 = (v & 31) * 4;
            float4 c = *(const float4*)(Cs + r * LDC + c4);
            const float g = wts[r];
            float* dst = res + (size_t)tok[r] * DDIM + bx * BN + c4;
            atomicAdd(dst + 0, (c.x + sbias[c4 + 0]) * g);
            atomicAdd(dst + 1, (c.y + sbias[c4 + 1]) * g);
            atomicAdd(dst + 2, (c.z + sbias[c4 + 2]) * g);
            atomicAdd(dst + 3, (c.w + sbias[c4 + 3]) * g);
        }
    }
}

// ================= launch =================
extern "C" void kernel_launch(void* const* d_in, const int* in_sizes, int n_in,
                              void* d_out, int out_size) {
    const float* x  = (const float*)d_in[0];
    const float* rw = (const float*)d_in[1];
    const float* w1 = (const float*)d_in[2];
    const float* b1 = (const float*)d_in[3];
    const float* w2 = (const float*)d_in[4];
    const float* b2 = (const float*)d_in[5];

    float* out = (float*)d_out;
    float* res = out;
    float* logits_out = nullptr;
    float* sel_out = nullptr;
    const long long TD = (long long)T_TOK * DDIM;
    if (out_size >= TD + T_TOK * NEXP) logits_out = out + TD;
    if (out_size >= TD + T_TOK * NEXP + NEXP * KSEL) sel_out = out + TD + T_TOK * NEXP;

    static cudaStream_t s1 = nullptr, s2 = nullptr;
    static cudaEvent_t ev0 = nullptr, ev1 = nullptr, ev2 = nullptr;
    if (!s1) {
        cudaStreamCreateWithFlags(&s1, cudaStreamNonBlocking);
        cudaStreamCreateWithFlags(&s2, cudaStreamNonBlocking);
        cudaEventCreateWithFlags(&ev0, cudaEventDisableTiming);
        cudaEventCreateWithFlags(&ev1, cudaEventDisableTiming);
        cudaEventCreateWithFlags(&ev2, cudaEventDisableTiming);
    }

    float* w1r; cudaGetSymbolAddress((void**)&w1r, g_w1r);
    float* w2r; cudaGetSymbolAddress((void**)&w2r, g_w2r);

    cudaMemsetAsync(res, 0, (size_t)TD * sizeof(float), 0);

    cudaEventRecord(ev0, 0);
    cudaStreamWaitEvent(s1, ev0, 0);
    cudaStreamWaitEvent(s2, ev0, 0);
    pack_w_kernel<<<dim3(HDIM / 32, DDIM / 32, NEXP), dim3(32, 8), 0, s1>>>(w1, w1r, DDIM, HDIM);
    pack_w_kernel<<<dim3(DDIM / 32, HDIM / 32, NEXP), dim3(32, 8), 0, s2>>>(w2, w2r, HDIM, DDIM);
    cudaEventRecord(ev1, s1);
    cudaEventRecord(ev2, s2);

    router_kernel<<<T_TOK, 256>>>(x, rw, logits_out);

    cudaFuncSetAttribute(topk_kernel, cudaFuncAttributeMaxDynamicSharedMemorySize,
                         T_TOK * (int)sizeof(unsigned long long));
    topk_kernel<<<NEXP, 1024, T_TOK * sizeof(unsigned long long)>>>(sel_out);

    gather_x_kernel<<<NEXP * KSEL, 256>>>(x);

    cudaFuncSetAttribute(moe_mma_kernel<true>,
                         cudaFuncAttributeMaxDynamicSharedMemorySize, GEMM_SMEM);
    cudaFuncSetAttribute(moe_mma_kernel<false>,
                         cudaFuncAttributeMaxDynamicSharedMemorySize, GEMM_SMEM);

    cudaStreamWaitEvent(0, ev1, 0);
    moe_mma_kernel<true><<<dim3(HDIM / BN, KSEL / BM, NEXP), 256, GEMM_SMEM>>>(w1r, b1, nullptr);
    cudaStreamWaitEvent(0, ev2, 0);
    moe_mma_kernel<false><<<dim3(DDIM / BN, KSEL / BM, NEXP), 256, GEMM_SMEM>>>(w2r, b2, res);
}

// round 8
// speedup vs baseline: 2.2026x; 1.0201x over previous
#include <cuda_runtime.h>
#include <cuda_bf16.h>
#include <math.h>
#include <stdint.h>

// Problem constants
#define T_TOK   8192
#define DDIM    1024
#define HDIM    4096
#define NEXP    8
#define KSEL    1024

// ---------------- device scratch ----------------
// Packed operand layout (A and B of MMA):
//   element (row r, col k): kb=k>>3, rb=r>>3, h=(k>>2)&1, rr=r&7, kk=k&3
//   float offset = (((kb*RB + rb)*2 + h)*8 + rr)*4 + kk   (RB = rows/8)
__device__ double g_probs[NEXP * T_TOK];
__device__ int    g_sel[NEXP * KSEL];
__device__ float  g_wts[NEXP * KSEL];
__device__ float  g_xg [(size_t)NEXP * KSEL * DDIM];
__device__ float  g_h  [(size_t)NEXP * KSEL * HDIM];
__device__ float  g_w1r[(size_t)NEXP * DDIM * HDIM];
__device__ float  g_w2r[(size_t)NEXP * HDIM * DDIM];
__device__ unsigned long long g_key0[NEXP * 8192];
__device__ unsigned long long g_key1[NEXP * 4096];

__device__ __forceinline__ uint32_t smem_u32(const void* p) {
    uint32_t a;
    asm("{ .reg .u64 t; cvta.to.shared.u64 t, %1; cvt.u32.u64 %0, t; }" : "=r"(a) : "l"(p));
    return a;
}
__device__ __forceinline__ void cpasync16(uint32_t dst, const void* src) {
    asm volatile("cp.async.cg.shared.global [%0], [%1], 16;" :: "r"(dst), "l"(src) : "memory");
}
__device__ __forceinline__ float tf32_rna(float v) {
    uint32_t o;
    asm("cvt.rna.tf32.f32 %0, %1;" : "=r"(o) : "f"(v));
    return __uint_as_float(o);
}
__device__ __forceinline__ float gelu_exact(float v) {
    return 0.5f * v * (1.0f + erff(v * 0.7071067811865476f));
}
__device__ __forceinline__ void ldsm_x4(uint32_t* r, uint32_t addr) {
    asm volatile("ldmatrix.sync.aligned.m8n8.x4.shared.b16 {%0,%1,%2,%3}, [%4];"
                 : "=r"(r[0]), "=r"(r[1]), "=r"(r[2]), "=r"(r[3]) : "r"(addr));
}
__device__ __forceinline__ void mma_16n8k8(float* d, const uint32_t* a, const uint32_t* b) {
    asm volatile(
        "mma.sync.aligned.m16n8k8.row.col.f32.tf32.tf32.f32 "
        "{%0,%1,%2,%3},{%4,%5,%6,%7},{%8,%9},{%0,%1,%2,%3};"
        : "+f"(d[0]), "+f"(d[1]), "+f"(d[2]), "+f"(d[3])
        : "r"(a[0]), "r"(a[1]), "r"(a[2]), "r"(a[3]), "r"(b[0]), "r"(b[1]));
}

// ================= router (fp64) =================
__global__ void router_kernel(const float* __restrict__ x,
                              const float* __restrict__ rw,
                              float* __restrict__ logits_out) {
    const int t = blockIdx.x;
    const int tid = threadIdx.x;
    const float* xr = x + (size_t)t * DDIM;
    double acc[NEXP];
#pragma unroll
    for (int e = 0; e < NEXP; e++) acc[e] = 0.0;
    const int k = tid * 4;
    float4 xv = *(const float4*)(xr + k);
#pragma unroll
    for (int e = 0; e < NEXP; e++) {
        float4 wv = *(const float4*)(rw + e * DDIM + k);
        acc[e] = fma((double)xv.x, (double)wv.x, acc[e]);
        acc[e] = fma((double)xv.y, (double)wv.y, acc[e]);
        acc[e] = fma((double)xv.z, (double)wv.z, acc[e]);
        acc[e] = fma((double)xv.w, (double)wv.w, acc[e]);
    }
#pragma unroll
    for (int e = 0; e < NEXP; e++)
#pragma unroll
        for (int o = 16; o; o >>= 1)
            acc[e] += __shfl_xor_sync(0xffffffffu, acc[e], o);
    __shared__ double red[NEXP][8];
    const int wid = tid >> 5, lid = tid & 31;
    if (lid == 0)
#pragma unroll
        for (int e = 0; e < NEXP; e++) red[e][wid] = acc[e];
    __syncthreads();
    if (tid == 0) {
        double l[NEXP], mx = -1e300;
#pragma unroll
        for (int e = 0; e < NEXP; e++) {
            double s = 0.0;
#pragma unroll
            for (int w = 0; w < 8; w++) s += red[e][w];
            l[e] = s; mx = fmax(mx, s);
        }
        double p[NEXP], sum = 0.0;
#pragma unroll
        for (int e = 0; e < NEXP; e++) { p[e] = exp(l[e] - mx); sum += p[e]; }
#pragma unroll
        for (int e = 0; e < NEXP; e++) {
            if (logits_out) logits_out[(size_t)t * NEXP + e] = (float)l[e];
            g_probs[(size_t)e * T_TOK + t] = p[e] / sum;
        }
    }
}

// ================= topk phase 1: sort 1024-chunks descending =================
__global__ void sort1024_kernel() {
    __shared__ unsigned long long key[1024];
    const int b = blockIdx.x;            // 64 blocks
    const int e = b >> 3, c = b & 7;
    const int tid = threadIdx.x;         // 512
#pragma unroll
    for (int q = 0; q < 2; q++) {
        const int i = tid + q * 512;
        const int gi = c * 1024 + i;
        double p = g_probs[(size_t)e * T_TOK + gi];
        unsigned long long db = __double_as_longlong(p);
        key[i] = (db & ~0x1FFFULL) | (unsigned long long)(8191 - gi);
    }
    __syncthreads();
    for (int k = 2; k <= 1024; k <<= 1) {
        for (int j = k >> 1; j > 0; j >>= 1) {
            const int i = ((tid & ~(j - 1)) << 1) | (tid & (j - 1));
            const int l = i | j;
            unsigned long long a = key[i], bb = key[l];
            bool descend = ((i & k) == 0);
            if ((a < bb) == descend) { key[i] = bb; key[l] = a; }
            __syncthreads();
        }
    }
    g_key0[(size_t)e * 8192 + c * 1024 + tid] = key[tid];
    g_key0[(size_t)e * 8192 + c * 1024 + tid + 512] = key[tid + 512];
}

// ================= topk merge: keep top-1024 of two sorted chunks =================
__global__ void merge_topk_kernel(const unsigned long long* __restrict__ src, int sstride,
                                  unsigned long long* __restrict__ dst, int dstride,
                                  int m, int final, float* __restrict__ sel_out) {
    __shared__ unsigned long long c[1024];
    const int b = blockIdx.x;            // NEXP*m
    const int e = b / m, p = b % m;
    const int tid = threadIdx.x;         // 512
    const unsigned long long* A = src + (size_t)e * sstride + (size_t)(2 * p) * 1024;
    const unsigned long long* B = A + 1024;
    {
        unsigned long long a0 = A[tid], b0 = B[1023 - tid];
        c[tid] = a0 > b0 ? a0 : b0;
        unsigned long long a1 = A[tid + 512], b1 = B[511 - tid];
        c[tid + 512] = a1 > b1 ? a1 : b1;
    }
    __syncthreads();
    for (int j = 512; j > 0; j >>= 1) {
        const int i = ((tid & ~(j - 1)) << 1) | (tid & (j - 1));
        const int l = i | j;
        unsigned long long x = c[i], y = c[l];
        if (x < y) { c[i] = y; c[l] = x; }
        __syncthreads();
    }
    if (!final) {
        dst[(size_t)e * dstride + p * 1024 + tid] = c[tid];
        dst[(size_t)e * dstride + p * 1024 + tid + 512] = c[tid + 512];
    } else {
#pragma unroll
        for (int q = 0; q < 2; q++) {
            const int i = tid + q * 512;
            unsigned long long kk = c[i];
            int idx = 8191 - (int)(kk & 0x1FFFULL);
            double val = __longlong_as_double((long long)(kk & ~0x1FFFULL));
            g_sel[e * KSEL + i] = idx;
            g_wts[e * KSEL + i] = (float)val;
            if (sel_out) sel_out[e * KSEL + i] = (float)idx;
        }
    }
}

// ================= gather A rows -> packed layout + rna =================
__global__ void gather_x_kernel(const float* __restrict__ x) {
    const int row = blockIdx.x;                 // 0..8191
    const int e = row >> 10, i = row & 1023;
    const int tok = g_sel[e * KSEL + i];
    const int tid = threadIdx.x;                // 0..255
    float4 v = ((const float4*)(x + (size_t)tok * DDIM))[tid];
    v.x = tf32_rna(v.x); v.y = tf32_rna(v.y);
    v.z = tf32_rna(v.z); v.w = tf32_rna(v.w);
    const int kb = tid >> 1, h = tid & 1;
    const int rb = i >> 3, rr = i & 7;
    const size_t off = ((((size_t)e * 128 + kb) * 128 + rb) * 2 + h) * 32 + rr * 4;
    *(float4*)(g_xg + off) = v;
}

// ================= weight pack: [E][K][N] -> packed(r=n, k) + rna =================
__global__ void pack_w_kernel(const float* __restrict__ src, float* __restrict__ dst,
                              int K, int N) {
    __shared__ float t[32][33];
    const int e = blockIdx.z;
    const int k0 = blockIdx.y * 32, n0 = blockIdx.x * 32;
    const int tx = threadIdx.x, ty = threadIdx.y;
    const float* s = src + (size_t)e * K * N;
#pragma unroll
    for (int j = 0; j < 4; j++)
        t[ty + 8 * j][tx] = s[(size_t)(k0 + ty + 8 * j) * N + n0 + tx];
    __syncthreads();
    float4 v;
    v.x = tf32_rna(t[ty * 4 + 0][tx]);
    v.y = tf32_rna(t[ty * 4 + 1][tx]);
    v.z = tf32_rna(t[ty * 4 + 2][tx]);
    v.w = tf32_rna(t[ty * 4 + 3][tx]);
    const int n = n0 + tx, kv = k0 + ty * 4;
    const int kb = kv >> 3, h = (kv >> 2) & 1;
    const int nb = n >> 3, nn = n & 7;
    const size_t KB = (size_t)(K >> 3), NB = (size_t)(N >> 3);
    const size_t off = ((((size_t)e * KB + kb) * NB + nb) * 2 + h) * 32 + nn * 4;
    *(float4*)(dst + off) = v;
}

// ================= mma.m16n8k8 tf32 GEMM, CTA 128x256, warp 64x64 =================
#define BM   128
#define BN   256
#define LDC  132
#define STAGES 3

#define OFF_TOK   0                  // 128 ints
#define OFF_WT    512                // 128 floats
#define OFF_BIAS  1024               // 256 floats
#define OFF_DATA  2048
#define A_BYTES_S 16384
#define B_BYTES_S 32768
#define STAGE_SZ  49152
#define GEMM_SMEM (OFF_DATA + STAGES * STAGE_SZ)   // 149504

template <bool G1>
__global__ __launch_bounds__(256, 1)
void moe_mma_kernel(const float* __restrict__ Bw,
                    const float* __restrict__ bias,
                    float* __restrict__ res) {
    extern __shared__ char smem[];
    const uint32_t sb = smem_u32(smem);
    const int tid = threadIdx.x;
    const int lane = tid & 31;
    const int e = blockIdx.z, by = blockIdx.y, bx = blockIdx.x;

    constexpr int KDIM = G1 ? DDIM : HDIM;
    constexpr int NTOT = G1 ? HDIM : DDIM;
    constexpr int KI = KDIM / 32;
    constexpr int RB = 128;
    constexpr int NB = NTOT / 8;

    const float* A = (G1 ? g_xg : g_h) + (size_t)e * KDIM * 1024;
    const float* B = Bw + (size_t)e * KDIM * NTOT;

    ((float*)(smem + OFF_BIAS))[tid] = bias[e * NTOT + bx * BN + tid];
    if (!G1 && tid < 128) {
        ((int*)(smem + OFF_TOK))[tid] = g_sel[e * KSEL + by * BM + tid];
        ((float*)(smem + OFF_WT))[tid] = g_wts[e * KSEL + by * BM + tid];
    }

    // 3072 chunks of 16B per stage: A 1024, B 2048.
    auto load_stage = [&](int kt, int buf) {
        const uint32_t st = sb + OFF_DATA + buf * STAGE_SZ;
#pragma unroll
        for (int i = 0; i < 12; i++) {
            const int c = tid + 256 * i;
            if (c < 1024) {
                const int kb = c >> 8, inner = c & 255;
                cpasync16(st + c * 16,
                          A + ((size_t)(kt * 4 + kb) * RB + by * 16) * 64 + inner * 4);
            } else {
                const int cb = c - 1024;
                const int kb = cb >> 9, inner = cb & 511;
                cpasync16(st + A_BYTES_S + cb * 16,
                          B + ((size_t)(kt * 4 + kb) * NB + bx * 32) * 64 + inner * 4);
            }
        }
        asm volatile("cp.async.commit_group;" ::: "memory");
    };

    const int wid = tid >> 5;
    const int wm = wid & 1, wn = wid >> 1;       // 2m x 4n, warp tile 64x64
    const int msel = lane >> 3;
    const uint32_t aoff = (uint32_t)(((msel & 1) * 16 + (msel >> 1) * 8 + (lane & 7)));
    const uint32_t boff = (uint32_t)(((msel >> 1) * 16 + (msel & 1) * 8 + (lane & 7)));
    const uint32_t aWarp = (uint32_t)(wm * 8 * 16 + aoff) * 16;
    const uint32_t bWarp = (uint32_t)(wn * 8 * 16 + boff) * 16;

    float acc[4][8][4];
#pragma unroll
    for (int i = 0; i < 4; i++)
#pragma unroll
        for (int j = 0; j < 8; j++)
#pragma unroll
            for (int q = 0; q < 4; q++) acc[i][j][q] = 0.f;

    load_stage(0, 0);
    load_stage(1, 1);

    int buf = 0;
#pragma unroll 1
    for (int kt = 0; kt < KI; kt++) {
        if (kt < KI - 1) asm volatile("cp.async.wait_group 1;" ::: "memory");
        else             asm volatile("cp.async.wait_group 0;" ::: "memory");
        __syncthreads();
        if (kt + 2 < KI) {
            int nb2 = buf + 2; if (nb2 >= STAGES) nb2 -= STAGES;
            load_stage(kt + 2, nb2);
        }
        const uint32_t st = sb + OFF_DATA + buf * STAGE_SZ;
#pragma unroll
        for (int ks = 0; ks < 4; ks++) {
            const uint32_t ksbA = st + ks * 4096;
            const uint32_t ksbB = st + A_BYTES_S + ks * 8192;
            uint32_t a[4][4], b[8][2];
#pragma unroll
            for (int mt = 0; mt < 4; mt++)
                ldsm_x4(a[mt], ksbA + aWarp + mt * 512);
#pragma unroll
            for (int p = 0; p < 4; p++) {
                uint32_t r[4];
                ldsm_x4(r, ksbB + bWarp + p * 512);
                b[2 * p][0] = r[0]; b[2 * p][1] = r[1];
                b[2 * p + 1][0] = r[2]; b[2 * p + 1][1] = r[3];
            }
#pragma unroll
            for (int mt = 0; mt < 4; mt++)
#pragma unroll
                for (int nt = 0; nt < 8; nt++)
                    mma_16n8k8(acc[mt][nt], a[mt], b[nt]);
        }
        if (++buf == STAGES) buf = 0;
    }
    __syncthreads();

    // ---- epilogue in two 128-col halves, staged through smem ----
    float* Cs = (float*)(smem + OFF_DATA);
    const float* sbias = (const float*)(smem + OFF_BIAS);
#pragma unroll 1
    for (int nh = 0; nh < 2; nh++) {
        if ((wn >> 1) == nh) {
#pragma unroll
            for (int mt = 0; mt < 4; mt++)
#pragma unroll
                for (int nt = 0; nt < 8; nt++) {
                    const int r0 = wm * 64 + mt * 16 + (lane >> 2);
                    const int cc = (wn & 1) * 64 + nt * 8 + (lane & 3) * 2;
                    *(float2*)&Cs[r0 * LDC + cc]       = make_float2(acc[mt][nt][0], acc[mt][nt][1]);
                    *(float2*)&Cs[(r0 + 8) * LDC + cc] = make_float2(acc[mt][nt][2], acc[mt][nt][3]);
                }
        }
        __syncthreads();
        if (G1) {
#pragma unroll
            for (int q = 0; q < 16; q++) {
                const int v = tid * 16 + q;
                const int r = v >> 5, c4 = (v & 31) * 4;
                float4 c = *(const float4*)(Cs + r * LDC + c4);
                c.x = tf32_rna(gelu_exact(c.x + sbias[nh * 128 + c4 + 0]));
                c.y = tf32_rna(gelu_exact(c.y + sbias[nh * 128 + c4 + 1]));
                c.z = tf32_rna(gelu_exact(c.z + sbias[nh * 128 + c4 + 2]));
                c.w = tf32_rna(gelu_exact(c.w + sbias[nh * 128 + c4 + 3]));
                const int n = bx * BN + nh * 128 + c4;
                const int kb = n >> 3, h = (n >> 2) & 1;
                const int m = by * BM + r;
                const int rb = m >> 3, rr = m & 7;
                const size_t off = ((((size_t)e * 512 + kb) * 128 + rb) * 2 + h) * 32 + rr * 4;
                *(float4*)(g_h + off) = c;
            }
        } else {
            const int* tok = (const int*)(smem + OFF_TOK);
            const float* wts = (const float*)(smem + OFF_WT);
#pragma unroll
            for (int q = 0; q < 16; q++) {
                const int v = tid * 16 + q;
                const int r = v >> 5, c4 = (v & 31) * 4;
                float4 c = *(const float4*)(Cs + r * LDC + c4);
                const float g = wts[r];
                float* dst = res + (size_t)tok[r] * DDIM + bx * BN + nh * 128 + c4;
                atomicAdd(dst + 0, (c.x + sbias[nh * 128 + c4 + 0]) * g);
                atomicAdd(dst + 1, (c.y + sbias[nh * 128 + c4 + 1]) * g);
                atomicAdd(dst + 2, (c.z + sbias[nh * 128 + c4 + 2]) * g);
                atomicAdd(dst + 3, (c.w + sbias[nh * 128 + c4 + 3]) * g);
            }
        }
        __syncthreads();
    }
}

// ================= launch =================
extern "C" void kernel_launch(void* const* d_in, const int* in_sizes, int n_in,
                              void* d_out, int out_size) {
    const float* x  = (const float*)d_in[0];
    const float* rw = (const float*)d_in[1];
    const float* w1 = (const float*)d_in[2];
    const float* b1 = (const float*)d_in[3];
    const float* w2 = (const float*)d_in[4];
    const float* b2 = (const float*)d_in[5];

    float* out = (float*)d_out;
    float* res = out;
    float* logits_out = nullptr;
    float* sel_out = nullptr;
    const long long TD = (long long)T_TOK * DDIM;
    if (out_size >= TD + T_TOK * NEXP) logits_out = out + TD;
    if (out_size >= TD + T_TOK * NEXP + NEXP * KSEL) sel_out = out + TD + T_TOK * NEXP;

    static cudaStream_t s1 = nullptr, s2 = nullptr;
    static cudaEvent_t ev0 = nullptr, ev1 = nullptr, ev2 = nullptr;
    if (!s1) {
        cudaStreamCreateWithFlags(&s1, cudaStreamNonBlocking);
        cudaStreamCreateWithFlags(&s2, cudaStreamNonBlocking);
        cudaEventCreateWithFlags(&ev0, cudaEventDisableTiming);
        cudaEventCreateWithFlags(&ev1, cudaEventDisableTiming);
        cudaEventCreateWithFlags(&ev2, cudaEventDisableTiming);
    }

    float* w1r; cudaGetSymbolAddress((void**)&w1r, g_w1r);
    float* w2r; cudaGetSymbolAddress((void**)&w2r, g_w2r);
    unsigned long long* k0; cudaGetSymbolAddress((void**)&k0, g_key0);
    unsigned long long* k1; cudaGetSymbolAddress((void**)&k1, g_key1);

    cudaMemsetAsync(res, 0, (size_t)TD * sizeof(float), 0);

    cudaEventRecord(ev0, 0);
    cudaStreamWaitEvent(s1, ev0, 0);
    cudaStreamWaitEvent(s2, ev0, 0);
    pack_w_kernel<<<dim3(HDIM / 32, DDIM / 32, NEXP), dim3(32, 8), 0, s1>>>(w1, w1r, DDIM, HDIM);
    pack_w_kernel<<<dim3(DDIM / 32, HDIM / 32, NEXP), dim3(32, 8), 0, s2>>>(w2, w2r, HDIM, DDIM);
    cudaEventRecord(ev1, s1);
    cudaEventRecord(ev2, s2);

    router_kernel<<<T_TOK, 256>>>(x, rw, logits_out);

    sort1024_kernel<<<64, 512>>>();
    merge_topk_kernel<<<32, 512>>>(k0, 8192, k1, 4096, 4, 0, nullptr);
    merge_topk_kernel<<<16, 512>>>(k1, 4096, k0, 8192, 2, 0, nullptr);
    merge_topk_kernel<<<8, 512>>>(k0, 8192, k1, 4096, 1, 1, sel_out);

    gather_x_kernel<<<NEXP * KSEL, 256>>>(x);

    cudaFuncSetAttribute(moe_mma_kernel<true>,
                         cudaFuncAttributeMaxDynamicSharedMemorySize, GEMM_SMEM);
    cudaFuncSetAttribute(moe_mma_kernel<false>,
                         cudaFuncAttributeMaxDynamicSharedMemorySize, GEMM_SMEM);

    cudaStreamWaitEvent(0, ev1, 0);
    moe_mma_kernel<true><<<dim3(HDIM / BN, KSEL / BM, NEXP), 256, GEMM_SMEM>>>(w1r, b1, nullptr);
    cudaStreamWaitEvent(0, ev2, 0);
    moe_mma_kernel<false><<<dim3(DDIM / BN, KSEL / BM, NEXP), 256, GEMM_SMEM>>>(w2r, b2, res);
}